// round 5
// baseline (speedup 1.0000x reference)
#include <cuda_runtime.h>
#include <math.h>

// Problem constants
#define B_    128
#define C_    2048
#define S_    196          // H*W = 14*14
#define HID_  1024
#define T_    20
#define M_    (B_*S_)      // 25088

// Scratch (allocation-free rule: __device__ globals)
__device__ float g_vi [M_*HID_];   // tanh(l1(v_i))  [M, HID]
__device__ float g_z  [M_*HID_];   // raw GEMM2 out  [M, HID]
__device__ float g_u0 [B_*HID_];
__device__ float g_u1 [B_*HID_];
__device__ float g_vqt[B_*HID_];

// ---------------------------------------------------------------------------
// u = mean over T of v_q   [B,T,HID] -> [B,HID]
// ---------------------------------------------------------------------------
__global__ void k_mean_vq(const float* __restrict__ vq, float* __restrict__ u) {
    int b = blockIdx.x;
    int h = threadIdx.x;                   // 1024 threads
    const float* p = vq + (size_t)b * T_ * HID_ + h;
    float s = 0.f;
#pragma unroll
    for (int t = 0; t < T_; ++t) s += p[(size_t)t * HID_];
    u[b * HID_ + h] = s * (1.0f / T_);
}

// ---------------------------------------------------------------------------
// Generic SGEMM: C[M,1024] = A[M,K] @ Bw[1024,K]^T  (+bias optional)
// 128x128 tile, BK=8, 256 threads, 8x8 per thread, double-buffered smem.
// M, K multiples of 128 / 8 (all true here) -> no bounds checks.
// ---------------------------------------------------------------------------
template<int KDIM, int WITH_BIAS>
__global__ __launch_bounds__(256)
void k_gemm_rowA(const float* __restrict__ A, const float* __restrict__ Bw,
                 const float* __restrict__ bias, float* __restrict__ Cout) {
    __shared__ float As[2][8][128];
    __shared__ float Bs[2][8][128];

    const int tid   = threadIdx.x;
    const int mBase = blockIdx.x * 128;
    const int nBase = blockIdx.y * 128;

    // load mapping: each thread loads one float4 along K
    const int lrow = tid >> 1;          // 0..127
    const int lcol = (tid & 1) * 4;     // 0 or 4
    const float* Aptr = A  + (size_t)(mBase + lrow) * KDIM + lcol;
    const float* Bptr = Bw + (size_t)(nBase + lrow) * KDIM + lcol;

    const int ty = tid >> 4;            // 0..15
    const int tx = tid & 15;            // 0..15

    float acc[8][8];
#pragma unroll
    for (int i = 0; i < 8; ++i)
#pragma unroll
        for (int j = 0; j < 8; ++j) acc[i][j] = 0.f;

    // prologue: stage 0
    {
        float4 av = *(const float4*)Aptr;
        float4 bv = *(const float4*)Bptr;
        As[0][lcol + 0][lrow] = av.x; As[0][lcol + 1][lrow] = av.y;
        As[0][lcol + 2][lrow] = av.z; As[0][lcol + 3][lrow] = av.w;
        Bs[0][lcol + 0][lrow] = bv.x; Bs[0][lcol + 1][lrow] = bv.y;
        Bs[0][lcol + 2][lrow] = bv.z; Bs[0][lcol + 3][lrow] = bv.w;
    }
    __syncthreads();

    const int NK = KDIM / 8;
    for (int kt = 0; kt < NK; ++kt) {
        float4 av, bv;
        if (kt + 1 < NK) {
            av = *(const float4*)(Aptr + (size_t)(kt + 1) * 8);
            bv = *(const float4*)(Bptr + (size_t)(kt + 1) * 8);
        }
        const int cur = kt & 1;
#pragma unroll
        for (int kk = 0; kk < 8; ++kk) {
            float a[8], b[8];
#pragma unroll
            for (int i = 0; i < 8; ++i) { a[i] = As[cur][kk][ty * 8 + i]; }
#pragma unroll
            for (int j = 0; j < 8; ++j) { b[j] = Bs[cur][kk][tx * 8 + j]; }
#pragma unroll
            for (int i = 0; i < 8; ++i)
#pragma unroll
                for (int j = 0; j < 8; ++j) acc[i][j] += a[i] * b[j];
        }
        if (kt + 1 < NK) {
            const int nxt = cur ^ 1;
            As[nxt][lcol + 0][lrow] = av.x; As[nxt][lcol + 1][lrow] = av.y;
            As[nxt][lcol + 2][lrow] = av.z; As[nxt][lcol + 3][lrow] = av.w;
            Bs[nxt][lcol + 0][lrow] = bv.x; Bs[nxt][lcol + 1][lrow] = bv.y;
            Bs[nxt][lcol + 2][lrow] = bv.z; Bs[nxt][lcol + 3][lrow] = bv.w;
        }
        __syncthreads();
    }

    // epilogue
    float bfrag[8];
    if (WITH_BIAS) {
#pragma unroll
        for (int j = 0; j < 8; ++j) bfrag[j] = bias[nBase + tx * 8 + j];
    }
    float* cp = Cout + (size_t)(mBase + ty * 8) * HID_ + nBase + tx * 8;
#pragma unroll
    for (int i = 0; i < 8; ++i) {
        float4 v0, v1;
        float r[8];
#pragma unroll
        for (int j = 0; j < 8; ++j) {
            float v = acc[i][j];
            if (WITH_BIAS) v += bfrag[j];
            r[j] = v;
        }
        v0.x = r[0]; v0.y = r[1]; v0.z = r[2]; v0.w = r[3];
        v1.x = r[4]; v1.y = r[5]; v1.z = r[6]; v1.w = r[7];
        *(float4*)(cp + (size_t)i * HID_)     = v0;
        *(float4*)(cp + (size_t)i * HID_ + 4) = v1;
    }
}

// ---------------------------------------------------------------------------
// GEMM1: vi = tanh( Avi @ l1_w^T + l1_b ), where Avi(r=b*S+s, c) = v_i[b,c,s]
// K = C_ = 2048. A loaded with strided addressing (contiguous in s).
// ---------------------------------------------------------------------------
__global__ __launch_bounds__(256)
void k_gemm1_tanh(const float* __restrict__ Vi, const float* __restrict__ l1w,
                  const float* __restrict__ l1b, float* __restrict__ Cout) {
    __shared__ float As[2][8][128];
    __shared__ float Bs[2][8][128];

    const int tid   = threadIdx.x;
    const int mBase = blockIdx.x * 128;
    const int nBase = blockIdx.y * 128;

    // A-side loaders: thread handles kk = tid>>5 (0..7), rows m4..m4+3
    const int kkL = tid >> 5;
    const int m4  = (tid & 31) * 4;
    const float* ap[4];
#pragma unroll
    for (int i = 0; i < 4; ++i) {
        int m  = mBase + m4 + i;
        int bb = m / S_;
        int ss = m - bb * S_;
        // base for c = kkL: v_i[bb, kkL, ss]; per stage add kt*8*S_
        ap[i] = Vi + (size_t)bb * C_ * S_ + (size_t)kkL * S_ + ss;
    }

    // B-side loaders (l1_w [HID, C] row-major, K = C_)
    const int brow = tid >> 1;
    const int bcol = (tid & 1) * 4;
    const float* Bptr = l1w + (size_t)(nBase + brow) * C_ + bcol;

    const int ty = tid >> 4;
    const int tx = tid & 15;

    float acc[8][8];
#pragma unroll
    for (int i = 0; i < 8; ++i)
#pragma unroll
        for (int j = 0; j < 8; ++j) acc[i][j] = 0.f;

    // prologue
    {
        float4 av;
        av.x = ap[0][0]; av.y = ap[1][0]; av.z = ap[2][0]; av.w = ap[3][0];
        *(float4*)&As[0][kkL][m4] = av;
        float4 bv = *(const float4*)Bptr;
        Bs[0][bcol + 0][brow] = bv.x; Bs[0][bcol + 1][brow] = bv.y;
        Bs[0][bcol + 2][brow] = bv.z; Bs[0][bcol + 3][brow] = bv.w;
    }
    __syncthreads();

    const int NK = C_ / 8;
    for (int kt = 0; kt < NK; ++kt) {
        float4 av, bv;
        if (kt + 1 < NK) {
            const size_t off = (size_t)(kt + 1) * 8 * S_;
            av.x = ap[0][off]; av.y = ap[1][off]; av.z = ap[2][off]; av.w = ap[3][off];
            bv = *(const float4*)(Bptr + (size_t)(kt + 1) * 8);
        }
        const int cur = kt & 1;
#pragma unroll
        for (int kk = 0; kk < 8; ++kk) {
            float a[8], b[8];
#pragma unroll
            for (int i = 0; i < 8; ++i) { a[i] = As[cur][kk][ty * 8 + i]; }
#pragma unroll
            for (int j = 0; j < 8; ++j) { b[j] = Bs[cur][kk][tx * 8 + j]; }
#pragma unroll
            for (int i = 0; i < 8; ++i)
#pragma unroll
                for (int j = 0; j < 8; ++j) acc[i][j] += a[i] * b[j];
        }
        if (kt + 1 < NK) {
            const int nxt = cur ^ 1;
            *(float4*)&As[nxt][kkL][m4] = av;
            Bs[nxt][bcol + 0][brow] = bv.x; Bs[nxt][bcol + 1][brow] = bv.y;
            Bs[nxt][bcol + 2][brow] = bv.z; Bs[nxt][bcol + 3][brow] = bv.w;
        }
        __syncthreads();
    }

    float bfrag[8];
#pragma unroll
    for (int j = 0; j < 8; ++j) bfrag[j] = l1b[nBase + tx * 8 + j];

    float* cp = Cout + (size_t)(mBase + ty * 8) * HID_ + nBase + tx * 8;
#pragma unroll
    for (int i = 0; i < 8; ++i) {
        float4 v0, v1;
        float r[8];
#pragma unroll
        for (int j = 0; j < 8; ++j) r[j] = tanhf(acc[i][j] + bfrag[j]);
        v0.x = r[0]; v0.y = r[1]; v0.z = r[2]; v0.w = r[3];
        v1.x = r[4]; v1.y = r[5]; v1.z = r[6]; v1.w = r[7];
        *(float4*)(cp + (size_t)i * HID_)     = v0;
        *(float4*)(cp + (size_t)i * HID_ + 4) = v1;
    }
}

// ---------------------------------------------------------------------------
// Fused attention tail: h_a = tanh(Z + vqt); p = softmax_s(h_a);
// u_out = u_in + sum_s p * vi.  Since h_a in (-1,1), exp() cannot overflow ->
// single pass: u_out = u_in + (sum_s e*vi) / (sum_s e), e = exp(h_a).
// One block per b (256 threads, 4 k's each); fully coalesced.
// ---------------------------------------------------------------------------
__global__ __launch_bounds__(256)
void k_attn(const float* __restrict__ Z, const float* __restrict__ vi,
            const float* __restrict__ vqt, const float* __restrict__ uin,
            float* __restrict__ uout) {
    const int b = blockIdx.x;
    const int t = threadIdx.x;
    float vq[4], ae[4], av[4];
#pragma unroll
    for (int j = 0; j < 4; ++j) {
        vq[j] = vqt[b * HID_ + t + j * 256];
        ae[j] = 0.f; av[j] = 0.f;
    }
    const float* zp = Z  + (size_t)b * S_ * HID_ + t;
    const float* vp = vi + (size_t)b * S_ * HID_ + t;
    for (int s = 0; s < S_; ++s) {
#pragma unroll
        for (int j = 0; j < 4; ++j) {
            float z = zp[(size_t)s * HID_ + j * 256];
            float v = vp[(size_t)s * HID_ + j * 256];
            float e = __expf(tanhf(z + vq[j]));
            ae[j] += e;
            av[j] += e * v;
        }
    }
#pragma unroll
    for (int j = 0; j < 4; ++j) {
        int idx = b * HID_ + t + j * 256;
        uout[idx] = uin[idx] + av[j] / ae[j];
    }
}

// ---------------------------------------------------------------------------
// Launch
// Inputs (metadata order): 0 v_i, 1 v_q, 2 l1_w, 3 l1_b, 4 w_vi0, 5 w_u0,
//                          6 b_u0, 7 w_vi1, 8 w_u1, 9 b_u1
// ---------------------------------------------------------------------------
extern "C" void kernel_launch(void* const* d_in, const int* in_sizes, int n_in,
                              void* d_out, int out_size) {
    const float* v_i  = (const float*)d_in[0];
    const float* v_q  = (const float*)d_in[1];
    const float* l1_w = (const float*)d_in[2];
    const float* l1_b = (const float*)d_in[3];
    const float* w_vi0= (const float*)d_in[4];
    const float* w_u0 = (const float*)d_in[5];
    const float* b_u0 = (const float*)d_in[6];
    const float* w_vi1= (const float*)d_in[7];
    const float* w_u1 = (const float*)d_in[8];
    const float* b_u1 = (const float*)d_in[9];
    float* out = (float*)d_out;

    float *p_vi, *p_z, *p_u0, *p_u1, *p_vqt;
    cudaGetSymbolAddress((void**)&p_vi,  g_vi);
    cudaGetSymbolAddress((void**)&p_z,   g_z);
    cudaGetSymbolAddress((void**)&p_u0,  g_u0);
    cudaGetSymbolAddress((void**)&p_u1,  g_u1);
    cudaGetSymbolAddress((void**)&p_vqt, g_vqt);

    dim3 gBig(M_ / 128, HID_ / 128);   // 196 x 8
    dim3 gSmall(1, HID_ / 128);        // 1 x 8 (M = B_ = 128)

    // u0 = mean_t v_q
    k_mean_vq<<<B_, HID_>>>(v_q, p_u0);

    // vi = tanh(l1(v_i))
    k_gemm1_tanh<<<gBig, 256>>>(v_i, l1_w, l1_b, p_vi);

    // hop 0
    k_gemm_rowA<HID_, 0><<<gBig, 256>>>(p_vi, w_vi0, nullptr, p_z);
    k_gemm_rowA<HID_, 1><<<gSmall, 256>>>(p_u0, w_u0, b_u0, p_vqt);
    k_attn<<<B_, 256>>>(p_z, p_vi, p_vqt, p_u0, p_u1);

    // hop 1
    k_gemm_rowA<HID_, 0><<<gBig, 256>>>(p_vi, w_vi1, nullptr, p_z);
    k_gemm_rowA<HID_, 1><<<gSmall, 256>>>(p_u1, w_u1, b_u1, p_vqt);
    k_attn<<<B_, 256>>>(p_z, p_vi, p_vqt, p_u1, out);
}

// round 8
// speedup vs baseline: 1.4339x; 1.4339x over previous
#include <cuda_runtime.h>
#include <cuda_bf16.h>
#include <math.h>
#include <cstdint>

// Problem constants
#define B_    128
#define C_    2048
#define S_    196          // H*W = 14*14
#define HID_  1024
#define T_    20
#define M_    (B_*S_)      // 25088

// ---------------------------------------------------------------------------
// Scratch (allocation-free rule: __device__ globals)
// ---------------------------------------------------------------------------
__device__ __nv_bfloat16 g_a1h[(size_t)M_*C_];    // v_i transposed, bf16 hi  [M,2048]
__device__ __nv_bfloat16 g_a1l[(size_t)M_*C_];    // v_i transposed, bf16 lo
__device__ __nv_bfloat16 g_vih[(size_t)M_*HID_];  // vi = tanh(l1), bf16 hi   [M,1024]
__device__ __nv_bfloat16 g_vil[(size_t)M_*HID_];  // vi lo
__device__ float         g_z  [(size_t)M_*HID_];  // hop GEMM out (fp32)
__device__ __nv_bfloat16 g_l1wh[(size_t)HID_*C_];
__device__ __nv_bfloat16 g_l1wl[(size_t)HID_*C_];
__device__ __nv_bfloat16 g_w0h[(size_t)HID_*HID_];
__device__ __nv_bfloat16 g_w0l[(size_t)HID_*HID_];
__device__ __nv_bfloat16 g_w1h[(size_t)HID_*HID_];
__device__ __nv_bfloat16 g_w1l[(size_t)HID_*HID_];
__device__ float g_u0 [B_*HID_];
__device__ float g_u1 [B_*HID_];
__device__ float g_vqt[B_*HID_];

// ---------------------------------------------------------------------------
// Portable (non-arch-specific) PTX helpers: ldmatrix / mma.sync / cp.async
// ---------------------------------------------------------------------------
__device__ __forceinline__ uint32_t smem_to_u32(const void* p) {
    uint32_t a;
    asm("{ .reg .u64 tmp; cvta.to.shared.u64 tmp, %1; cvt.u32.u64 %0, tmp; }"
        : "=r"(a) : "l"(p));
    return a;
}
__device__ __forceinline__ void ldmatrix_x4(uint32_t* r, uint32_t addr) {
    asm volatile("ldmatrix.sync.aligned.m8n8.x4.shared.b16 {%0,%1,%2,%3}, [%4];"
        : "=r"(r[0]), "=r"(r[1]), "=r"(r[2]), "=r"(r[3]) : "r"(addr));
}
__device__ __forceinline__ void mma_16816(float* d, const uint32_t* a, const uint32_t* b) {
    asm volatile(
        "mma.sync.aligned.m16n8k16.row.col.f32.bf16.bf16.f32 "
        "{%0,%1,%2,%3}, {%4,%5,%6,%7}, {%8,%9}, {%0,%1,%2,%3};"
        : "+f"(d[0]), "+f"(d[1]), "+f"(d[2]), "+f"(d[3])
        : "r"(a[0]), "r"(a[1]), "r"(a[2]), "r"(a[3]), "r"(b[0]), "r"(b[1]));
}
__device__ __forceinline__ void ldgsts16(uint32_t dst, const void* src) {
    asm volatile("cp.async.cg.shared.global [%0], [%1], 16;" :: "r"(dst), "l"(src) : "memory");
}
#define CP_COMMIT() asm volatile("cp.async.commit_group;" ::: "memory")
#define CP_WAIT1()  asm volatile("cp.async.wait_group 1;" ::: "memory")

// ---------------------------------------------------------------------------
// HMMA GEMM: C[M,1024] = A[M,K] @ B[1024,K]^T, A/B as bf16 hi/lo pairs,
// 3-term product (AhBh + AhBl + AlBh), fp32 accumulators in registers.
// CTA tile 128x128, K-chunk 32, 8 warps (2x4, 64x32 warp tiles),
// 3-stage cp.async pipeline.  Row stride in smem = 40 bf16 (80B, padded:
// 8 rows cover all 8 16B-bank groups -> conflict-free ldmatrix).
// EPI=0: fp32 out.  EPI=1: tanh(C+bias) -> bf16 hi/lo pair outputs.
// ---------------------------------------------------------------------------
#define RS     40                 // padded row stride (elems)
#define ST_E   (4*128*RS)         // elems per stage (Ah,Al,Bh,Bl)
#define OFF_AL (128*RS)
#define OFF_BH (2*128*RS)
#define OFF_BL (3*128*RS)
#define SMEM_DYN (3 * ST_E * 2)   // 122880 bytes

template<int EPI>
__global__ __launch_bounds__(256, 1)
void k_mma_gemm(const __nv_bfloat16* __restrict__ Ah, const __nv_bfloat16* __restrict__ Al,
                const __nv_bfloat16* __restrict__ Bh, const __nv_bfloat16* __restrict__ Bl,
                const float* __restrict__ bias,
                float* __restrict__ outF,
                __nv_bfloat16* __restrict__ outH, __nv_bfloat16* __restrict__ outL,
                int K, int NK)
{
    extern __shared__ __nv_bfloat16 sm[];
    const uint32_t sbase = smem_to_u32(sm);
    const int tid  = threadIdx.x;
    const int wid  = tid >> 5, lane = tid & 31;
    const int wm   = wid >> 2, wn = wid & 3;            // warp grid 2x4
    const int gg   = lane >> 2, tig = lane & 3;
    const int nBase = blockIdx.x * 128;
    const int mBase = blockIdx.y * 128;

    // stage-loader indices (512 16B-chunks per array; 2 per thread)
    const int lrow0 = tid >> 2,          lseg0 = tid & 3;
    const int lrow1 = (tid + 256) >> 2,  lseg1 = (tid + 256) & 3;

    // ldmatrix thread-address components
    const int a_row  = wm * 64 + ((lane >> 3) & 1) * 8 + (lane & 7);  // + mi*16
    const int a_col  = (lane >> 4) * 8;                               // + k0
    const int b_row  = wn * 32 + (lane >> 4) * 8 + (lane & 7);        // + nb*16
    const int b_col  = ((lane >> 3) & 1) * 8;                         // + k0

    float acc[4][4][4];
#pragma unroll
    for (int mi = 0; mi < 4; ++mi)
#pragma unroll
        for (int ni = 0; ni < 4; ++ni)
#pragma unroll
            for (int c = 0; c < 4; ++c) acc[mi][ni][c] = 0.f;

    auto load_stage = [&](int st, int kt) {
        const int koff = kt * 32;
        const uint32_t s0 = sbase + (uint32_t)(st * ST_E + lrow0 * RS + lseg0 * 8) * 2;
        const uint32_t s1 = sbase + (uint32_t)(st * ST_E + lrow1 * RS + lseg1 * 8) * 2;
        const size_t ga0 = (size_t)(mBase + lrow0) * K + koff + lseg0 * 8;
        const size_t ga1 = (size_t)(mBase + lrow1) * K + koff + lseg1 * 8;
        const size_t gb0 = (size_t)(nBase + lrow0) * K + koff + lseg0 * 8;
        const size_t gb1 = (size_t)(nBase + lrow1) * K + koff + lseg1 * 8;
        ldgsts16(s0,              Ah + ga0);  ldgsts16(s1,              Ah + ga1);
        ldgsts16(s0 + OFF_AL * 2, Al + ga0);  ldgsts16(s1 + OFF_AL * 2, Al + ga1);
        ldgsts16(s0 + OFF_BH * 2, Bh + gb0);  ldgsts16(s1 + OFF_BH * 2, Bh + gb1);
        ldgsts16(s0 + OFF_BL * 2, Bl + gb0);  ldgsts16(s1 + OFF_BL * 2, Bl + gb1);
    };

    load_stage(0, 0); CP_COMMIT();
    load_stage(1, 1); CP_COMMIT();

    for (int kt = 0; kt < NK; ++kt) {
        const int st = kt % 3;
        CP_WAIT1();
        __syncthreads();

        const uint32_t stb = sbase + (uint32_t)(st * ST_E) * 2;
#pragma unroll
        for (int half = 0; half < 2; ++half) {
            const int k0 = half * 16;
            uint32_t ah[4][4], al[4][4], bh[2][4], bl[2][4];
#pragma unroll
            for (int mi = 0; mi < 4; ++mi) {
                uint32_t ad = stb + (uint32_t)((a_row + mi * 16) * RS + k0 + a_col) * 2;
                ldmatrix_x4(ah[mi], ad);
                ldmatrix_x4(al[mi], ad + OFF_AL * 2);
            }
#pragma unroll
            for (int nb = 0; nb < 2; ++nb) {
                uint32_t bd = stb + (uint32_t)(OFF_BH + (b_row + nb * 16) * RS + k0 + b_col) * 2;
                ldmatrix_x4(bh[nb], bd);
                ldmatrix_x4(bl[nb], bd + (OFF_BL - OFF_BH) * 2);
            }
#pragma unroll
            for (int mi = 0; mi < 4; ++mi)
#pragma unroll
                for (int ni = 0; ni < 4; ++ni) {
                    const uint32_t* fbh = &bh[ni >> 1][(ni & 1) * 2];
                    const uint32_t* fbl = &bl[ni >> 1][(ni & 1) * 2];
                    mma_16816(acc[mi][ni], ah[mi], fbh);
                    mma_16816(acc[mi][ni], ah[mi], fbl);
                    mma_16816(acc[mi][ni], al[mi], fbh);
                }
        }

        // all smem reads for stage (kt+2)%3 finished at iteration kt-1,
        // and every warp passed this iteration's __syncthreads -> safe refill
        if (kt + 2 < NK) load_stage((kt + 2) % 3, kt + 2);
        CP_COMMIT();
    }

    // epilogue (register accumulators -> gmem)
#pragma unroll
    for (int mi = 0; mi < 4; ++mi) {
#pragma unroll
        for (int ni = 0; ni < 4; ++ni) {
            const int row = mBase + wm * 64 + mi * 16 + gg;
            const int col = nBase + wn * 32 + ni * 8 + tig * 2;
            if (EPI == 0) {
                float2 v0 = make_float2(acc[mi][ni][0], acc[mi][ni][1]);
                float2 v1 = make_float2(acc[mi][ni][2], acc[mi][ni][3]);
                *(float2*)(outF + (size_t)row * HID_ + col)       = v0;
                *(float2*)(outF + (size_t)(row + 8) * HID_ + col) = v1;
            } else {
                const float b0 = bias[col], b1 = bias[col + 1];
                float t0 = tanhf(acc[mi][ni][0] + b0);
                float t1 = tanhf(acc[mi][ni][1] + b1);
                float t2 = tanhf(acc[mi][ni][2] + b0);
                float t3 = tanhf(acc[mi][ni][3] + b1);
                __nv_bfloat16 h0 = __float2bfloat16(t0), h1 = __float2bfloat16(t1);
                __nv_bfloat16 h2 = __float2bfloat16(t2), h3 = __float2bfloat16(t3);
                __nv_bfloat16 l0 = __float2bfloat16(t0 - __bfloat162float(h0));
                __nv_bfloat16 l1 = __float2bfloat16(t1 - __bfloat162float(h1));
                __nv_bfloat16 l2 = __float2bfloat16(t2 - __bfloat162float(h2));
                __nv_bfloat16 l3 = __float2bfloat16(t3 - __bfloat162float(h3));
                const size_t o0 = (size_t)row * HID_ + col;
                const size_t o1 = (size_t)(row + 8) * HID_ + col;
                *(__nv_bfloat162*)(outH + o0) = __halves2bfloat162(h0, h1);
                *(__nv_bfloat162*)(outL + o0) = __halves2bfloat162(l0, l1);
                *(__nv_bfloat162*)(outH + o1) = __halves2bfloat162(h2, h3);
                *(__nv_bfloat162*)(outL + o1) = __halves2bfloat162(l2, l3);
            }
        }
    }
}

// ---------------------------------------------------------------------------
// u = mean over T of v_q
// ---------------------------------------------------------------------------
__global__ void k_mean_vq(const float* __restrict__ vq, float* __restrict__ u) {
    int b = blockIdx.x;
    int h = threadIdx.x;
    const float* p = vq + (size_t)b * T_ * HID_ + h;
    float s = 0.f;
#pragma unroll
    for (int t = 0; t < T_; ++t) s += p[(size_t)t * HID_];
    u[b * HID_ + h] = s * (1.0f / T_);
}

// ---------------------------------------------------------------------------
// fp32 -> bf16 hi/lo elementwise split
// ---------------------------------------------------------------------------
__global__ void k_split(const float* __restrict__ x,
                        __nv_bfloat16* __restrict__ h, __nv_bfloat16* __restrict__ l,
                        int n) {
    int i = blockIdx.x * 256 + threadIdx.x;
    if (i < n) {
        float v = x[i];
        __nv_bfloat16 hi = __float2bfloat16(v);
        h[i] = hi;
        l[i] = __float2bfloat16(v - __bfloat162float(hi));
    }
}

// ---------------------------------------------------------------------------
// v_i [B,C,S] -> A1 [B*S, C] bf16 hi/lo (transpose + split), 32x32 smem tiles
// ---------------------------------------------------------------------------
__global__ void k_conv_vi(const float* __restrict__ vi,
                          __nv_bfloat16* __restrict__ h, __nv_bfloat16* __restrict__ l) {
    __shared__ float t[32][33];
    const int b = blockIdx.x, c0 = blockIdx.y * 32, s0 = blockIdx.z * 32;
    const int tx = threadIdx.x, ty = threadIdx.y;
    const float* src = vi + (size_t)b * C_ * S_;
#pragma unroll
    for (int i = 0; i < 4; ++i) {
        int c = c0 + ty + i * 8;
        int s = s0 + tx;
        t[ty + i * 8][tx] = (s < S_) ? src[(size_t)c * S_ + s] : 0.f;
    }
    __syncthreads();
#pragma unroll
    for (int i = 0; i < 4; ++i) {
        int s = s0 + ty + i * 8;
        if (s < S_) {
            int c = c0 + tx;
            float v = t[tx][ty + i * 8];
            __nv_bfloat16 hi = __float2bfloat16(v);
            size_t o = ((size_t)b * S_ + s) * C_ + c;
            h[o] = hi;
            l[o] = __float2bfloat16(v - __bfloat162float(hi));
        }
    }
}

// ---------------------------------------------------------------------------
// vqt = u @ w_u^T + b_u   [128,1024] x [1024,1024]^T — 64 blocks, 2 b each
// ---------------------------------------------------------------------------
__global__ __launch_bounds__(256)
void k_vqt(const float* __restrict__ u, const float* __restrict__ wu,
           const float* __restrict__ bu, float* __restrict__ vqt) {
    __shared__ float us[2][HID_];
    const int b0 = blockIdx.x * 2;
    const int tid = threadIdx.x;
    for (int i = tid; i < 2 * HID_; i += 256)
        us[i >> 10][i & 1023] = u[(size_t)b0 * HID_ + i];
    __syncthreads();
    const int h0 = tid * 4;
    float acc[2][4] = {};
    for (int k = 0; k < HID_; k += 4) {
        float4 u0 = *(const float4*)&us[0][k];
        float4 u1 = *(const float4*)&us[1][k];
#pragma unroll
        for (int j = 0; j < 4; ++j) {
            float4 w = *(const float4*)&wu[(size_t)(h0 + j) * HID_ + k];
            acc[0][j] += u0.x * w.x + u0.y * w.y + u0.z * w.z + u0.w * w.w;
            acc[1][j] += u1.x * w.x + u1.y * w.y + u1.z * w.z + u1.w * w.w;
        }
    }
#pragma unroll
    for (int j = 0; j < 4; ++j) {
        float bb = bu[h0 + j];
        vqt[(size_t)b0 * HID_ + h0 + j]       = acc[0][j] + bb;
        vqt[(size_t)(b0 + 1) * HID_ + h0 + j] = acc[1][j] + bb;
    }
}

// ---------------------------------------------------------------------------
// Fused attention tail (single pass; tanh bounds exp, no max needed):
// u_out = u_in + (sum_s e*vi) / (sum_s e), e = exp(tanh(z + vqt))
// ---------------------------------------------------------------------------
__global__ __launch_bounds__(256)
void k_attn(const float* __restrict__ Z,
            const __nv_bfloat16* __restrict__ vh, const __nv_bfloat16* __restrict__ vl,
            const float* __restrict__ vqt, const float* __restrict__ uin,
            float* __restrict__ uout) {
    const int b = blockIdx.x;
    const int t = threadIdx.x;
    float vq[4], ae[4], av[4];
#pragma unroll
    for (int j = 0; j < 4; ++j) {
        vq[j] = vqt[b * HID_ + t + j * 256];
        ae[j] = 0.f; av[j] = 0.f;
    }
    const float*         zp  = Z  + (size_t)b * S_ * HID_ + t;
    const __nv_bfloat16* vph = vh + (size_t)b * S_ * HID_ + t;
    const __nv_bfloat16* vpl = vl + (size_t)b * S_ * HID_ + t;
    for (int s = 0; s < S_; ++s) {
#pragma unroll
        for (int j = 0; j < 4; ++j) {
            size_t off = (size_t)s * HID_ + j * 256;
            float z = zp[off];
            float v = __bfloat162float(vph[off]) + __bfloat162float(vpl[off]);
            float e = __expf(tanhf(z + vq[j]));
            ae[j] += e;
            av[j] += e * v;
        }
    }
#pragma unroll
    for (int j = 0; j < 4; ++j) {
        int idx = b * HID_ + t + j * 256;
        uout[idx] = uin[idx] + av[j] / ae[j];
    }
}

// ---------------------------------------------------------------------------
// Launch.  Inputs: 0 v_i, 1 v_q, 2 l1_w, 3 l1_b, 4 w_vi0, 5 w_u0, 6 b_u0,
//                  7 w_vi1, 8 w_u1, 9 b_u1
// ---------------------------------------------------------------------------
extern "C" void kernel_launch(void* const* d_in, const int* in_sizes, int n_in,
                              void* d_out, int out_size) {
    const float* v_i  = (const float*)d_in[0];
    const float* v_q  = (const float*)d_in[1];
    const float* l1_w = (const float*)d_in[2];
    const float* l1_b = (const float*)d_in[3];
    const float* w_vi0= (const float*)d_in[4];
    const float* w_u0 = (const float*)d_in[5];
    const float* b_u0 = (const float*)d_in[6];
    const float* w_vi1= (const float*)d_in[7];
    const float* w_u1 = (const float*)d_in[8];
    const float* b_u1 = (const float*)d_in[9];
    float* out = (float*)d_out;

    __nv_bfloat16 *p_a1h, *p_a1l, *p_vih, *p_vil, *p_l1wh, *p_l1wl;
    __nv_bfloat16 *p_w0h, *p_w0l, *p_w1h, *p_w1l;
    float *p_z, *p_u0, *p_u1, *p_vqt;
    cudaGetSymbolAddress((void**)&p_a1h,  g_a1h);
    cudaGetSymbolAddress((void**)&p_a1l,  g_a1l);
    cudaGetSymbolAddress((void**)&p_vih,  g_vih);
    cudaGetSymbolAddress((void**)&p_vil,  g_vil);
    cudaGetSymbolAddress((void**)&p_l1wh, g_l1wh);
    cudaGetSymbolAddress((void**)&p_l1wl, g_l1wl);
    cudaGetSymbolAddress((void**)&p_w0h,  g_w0h);
    cudaGetSymbolAddress((void**)&p_w0l,  g_w0l);
    cudaGetSymbolAddress((void**)&p_w1h,  g_w1h);
    cudaGetSymbolAddress((void**)&p_w1l,  g_w1l);
    cudaGetSymbolAddress((void**)&p_z,    g_z);
    cudaGetSymbolAddress((void**)&p_u0,   g_u0);
    cudaGetSymbolAddress((void**)&p_u1,   g_u1);
    cudaGetSymbolAddress((void**)&p_vqt,  g_vqt);

    cudaFuncSetAttribute(k_mma_gemm<0>, cudaFuncAttributeMaxDynamicSharedMemorySize, SMEM_DYN);
    cudaFuncSetAttribute(k_mma_gemm<1>, cudaFuncAttributeMaxDynamicSharedMemorySize, SMEM_DYN);

    const dim3 gGemm(HID_ / 128, M_ / 128);   // x = n-tile (8, fast) -> A tiles L2-shared

    // u0 = mean_t v_q
    k_mean_vq<<<B_, HID_>>>(v_q, p_u0);

    // bf16 hi/lo conversions
    k_split<<<(HID_ * C_ + 255) / 256, 256>>>(l1_w, p_l1wh, p_l1wl, HID_ * C_);
    k_split<<<(HID_ * HID_ + 255) / 256, 256>>>(w_vi0, p_w0h, p_w0l, HID_ * HID_);
    k_split<<<(HID_ * HID_ + 255) / 256, 256>>>(w_vi1, p_w1h, p_w1l, HID_ * HID_);
    {
        dim3 g(B_, C_ / 32, (S_ + 31) / 32);
        k_conv_vi<<<g, dim3(32, 8)>>>(v_i, p_a1h, p_a1l);
    }

    // GEMM1: vi = tanh(A1 @ l1_w^T + l1_b) -> bf16 hi/lo
    k_mma_gemm<1><<<gGemm, 256, SMEM_DYN>>>(p_a1h, p_a1l, p_l1wh, p_l1wl,
                                            l1_b, nullptr, p_vih, p_vil, C_, C_ / 32);

    // hop 0
    k_mma_gemm<0><<<gGemm, 256, SMEM_DYN>>>(p_vih, p_vil, p_w0h, p_w0l,
                                            nullptr, p_z, nullptr, nullptr, HID_, HID_ / 32);
    k_vqt<<<B_ / 2, 256>>>(p_u0, w_u0, b_u0, p_vqt);
    k_attn<<<B_, 256>>>(p_z, p_vih, p_vil, p_vqt, p_u0, p_u1);

    // hop 1
    k_mma_gemm<0><<<gGemm, 256, SMEM_DYN>>>(p_vih, p_vil, p_w1h, p_w1l,
                                            nullptr, p_z, nullptr, nullptr, HID_, HID_ / 32);
    k_vqt<<<B_ / 2, 256>>>(p_u1, w_u1, b_u1, p_vqt);
    k_attn<<<B_, 256>>>(p_z, p_vih, p_vil, p_vqt, p_u1, out);
}

// round 9
// speedup vs baseline: 2.1808x; 1.5209x over previous
#include <cuda_runtime.h>
#include <cuda_bf16.h>
#include <math.h>
#include <cstdint>

// Problem constants
#define B_    128
#define C_    2048
#define S_    196          // H*W = 14*14
#define HID_  1024
#define T_    20
#define M_    (B_*S_)      // 25088

// ---------------------------------------------------------------------------
// Scratch (allocation-free rule: __device__ globals)
// ---------------------------------------------------------------------------
__device__ __nv_bfloat16 g_a1h[(size_t)M_*C_];    // v_i transposed, bf16 hi  [M,2048]
__device__ __nv_bfloat16 g_a1l[(size_t)M_*C_];    // v_i transposed, bf16 lo
__device__ __nv_bfloat16 g_vih[(size_t)M_*HID_];  // vi = tanh(l1), bf16 hi   [M,1024]
__device__ __nv_bfloat16 g_vil[(size_t)M_*HID_];  // vi lo
__device__ float         g_z  [(size_t)M_*HID_];  // hop GEMM out (fp32)
__device__ __nv_bfloat16 g_l1wh[(size_t)HID_*C_];
__device__ __nv_bfloat16 g_l1wl[(size_t)HID_*C_];
__device__ __nv_bfloat16 g_w0h[(size_t)HID_*HID_];
__device__ __nv_bfloat16 g_w0l[(size_t)HID_*HID_];
__device__ __nv_bfloat16 g_w1h[(size_t)HID_*HID_];
__device__ __nv_bfloat16 g_w1l[(size_t)HID_*HID_];
__device__ float g_u0 [B_*HID_];
__device__ float g_u1 [B_*HID_];
__device__ float g_vqt[B_*HID_];

// ---------------------------------------------------------------------------
// Portable (non-arch-specific) PTX helpers: ldmatrix / mma.sync / cp.async
// ---------------------------------------------------------------------------
__device__ __forceinline__ uint32_t smem_to_u32(const void* p) {
    uint32_t a;
    asm("{ .reg .u64 tmp; cvta.to.shared.u64 tmp, %1; cvt.u32.u64 %0, tmp; }"
        : "=r"(a) : "l"(p));
    return a;
}
__device__ __forceinline__ void ldmatrix_x4(uint32_t* r, uint32_t addr) {
    asm volatile("ldmatrix.sync.aligned.m8n8.x4.shared.b16 {%0,%1,%2,%3}, [%4];"
        : "=r"(r[0]), "=r"(r[1]), "=r"(r[2]), "=r"(r[3]) : "r"(addr));
}
__device__ __forceinline__ void mma_16816(float* d, const uint32_t* a, const uint32_t* b) {
    asm volatile(
        "mma.sync.aligned.m16n8k16.row.col.f32.bf16.bf16.f32 "
        "{%0,%1,%2,%3}, {%4,%5,%6,%7}, {%8,%9}, {%0,%1,%2,%3};"
        : "+f"(d[0]), "+f"(d[1]), "+f"(d[2]), "+f"(d[3])
        : "r"(a[0]), "r"(a[1]), "r"(a[2]), "r"(a[3]), "r"(b[0]), "r"(b[1]));
}
__device__ __forceinline__ void ldgsts16(uint32_t dst, const void* src) {
    asm volatile("cp.async.cg.shared.global [%0], [%1], 16;" :: "r"(dst), "l"(src) : "memory");
}
#define CP_COMMIT() asm volatile("cp.async.commit_group;" ::: "memory")
#define CP_WAIT1()  asm volatile("cp.async.wait_group 1;" ::: "memory")

// ---------------------------------------------------------------------------
// HMMA GEMM: C[M,1024] = A[M,K] @ B[1024,K]^T, A/B as bf16 hi/lo pairs,
// 3-term product (AhBh + AhBl + AlBh), fp32 accumulators in registers.
// CTA tile 128x128, K-chunk 32, 8 warps (2x4, 64x32 warp tiles),
// 3-stage cp.async pipeline, 2 CTAs per SM.
// SMEM layout per stage: A_pair[128][144B]  (bytes 0-63 = hi chunk, 64-127 =
// lo chunk, 16B pad), then B_pair likewise. 144B = 16B*9 -> (9r+c)%8=(r+c)%8:
// conflict-free for ldmatrix and cp.async, all 16B aligned.
// EPI=0: fp32 out.  EPI=1: tanh(C+bias) -> bf16 hi/lo pair outputs.
// ---------------------------------------------------------------------------
#define ROW_B    144
#define APAIR_B  (128*ROW_B)       // 18432
#define STAGE_B  (2*APAIR_B)       // 36864
#define SMEM_DYN (3*STAGE_B)       // 110592 (x2 CTAs = 216KB <= 228KB)

template<int EPI>
__global__ __launch_bounds__(256, 2)
void k_mma_gemm(const __nv_bfloat16* __restrict__ Ah, const __nv_bfloat16* __restrict__ Al,
                const __nv_bfloat16* __restrict__ Bh, const __nv_bfloat16* __restrict__ Bl,
                const float* __restrict__ bias,
                float* __restrict__ outF,
                __nv_bfloat16* __restrict__ outH, __nv_bfloat16* __restrict__ outL,
                int K, int NK)
{
    extern __shared__ char sm[];
    const uint32_t sbase = smem_to_u32(sm);
    const int tid  = threadIdx.x;
    const int wid  = tid >> 5, lane = tid & 31;
    const int wm   = wid >> 2, wn = wid & 3;            // warp grid 2x4
    const int gg   = lane >> 2, tig = lane & 3;
    const int nBase = blockIdx.x * 128;
    const int mBase = blockIdx.y * 128;

    // loader decomposition: gidx = tid + i*256, i=0..7.
    // cc = gidx&7 == tid&7 (loop-invariant); rows advance by 32 per i.
    const int cc   = tid & 7;            // 0-3 -> hi chunk, 4-7 -> lo chunk
    const int seg  = cc & 3;             // 16B segment within 64B chunk
    const int lrow = tid >> 3;           // 0..31
    const __nv_bfloat16* srcA = (cc < 4) ? Ah : Al;
    const __nv_bfloat16* srcB = (cc < 4) ? Bh : Bl;

    // ldmatrix thread-address components (identical fragment mapping to R8)
    const int a_row  = wm * 64 + ((lane >> 3) & 1) * 8 + (lane & 7);  // + mi*16
    const int a_col  = (lane >> 4) * 8;                               // + k0
    const int b_row  = wn * 32 + (lane >> 4) * 8 + (lane & 7);        // + nb*16
    const int b_col  = ((lane >> 3) & 1) * 8;                         // + k0

    float acc[4][4][4];
#pragma unroll
    for (int mi = 0; mi < 4; ++mi)
#pragma unroll
        for (int ni = 0; ni < 4; ++ni)
#pragma unroll
            for (int c = 0; c < 4; ++c) acc[mi][ni][c] = 0.f;

    auto load_stage = [&](int st, int kt) {
        const int koff = kt * 32 + seg * 8;
        const uint32_t db = sbase + st * STAGE_B + cc * 16;
#pragma unroll
        for (int i = 0; i < 4; ++i) {
            const int row = lrow + i * 32;
            ldgsts16(db + row * ROW_B,           srcA + (size_t)(mBase + row) * K + koff);
            ldgsts16(db + APAIR_B + row * ROW_B, srcB + (size_t)(nBase + row) * K + koff);
        }
    };

    load_stage(0, 0); CP_COMMIT();
    load_stage(1, 1); CP_COMMIT();

    for (int kt = 0; kt < NK; ++kt) {
        const int st = kt % 3;
        CP_WAIT1();                       // chunk kt resident
        __syncthreads();

        // prefetch FIRST so cp.async overlaps the MMA block below.
        // stage (kt+2)%3 was consumed at iter kt-1; the barrier above makes
        // the overwrite safe.
        if (kt + 2 < NK) load_stage((kt + 2) % 3, kt + 2);
        CP_COMMIT();                      // uniform group count per iteration

        const uint32_t stb = sbase + st * STAGE_B;
#pragma unroll
        for (int half = 0; half < 2; ++half) {
            const int k0 = half * 16;
            uint32_t bh[2][4], bl[2][4];
#pragma unroll
            for (int nb = 0; nb < 2; ++nb) {
                const uint32_t bd = stb + APAIR_B
                    + (uint32_t)(b_row + nb * 16) * ROW_B + (k0 + b_col) * 2;
                ldmatrix_x4(bh[nb], bd);
                ldmatrix_x4(bl[nb], bd + 64);
            }
#pragma unroll
            for (int mi = 0; mi < 4; ++mi) {
                uint32_t ah[4], al[4];
                const uint32_t ad = stb
                    + (uint32_t)(a_row + mi * 16) * ROW_B + (k0 + a_col) * 2;
                ldmatrix_x4(ah, ad);
                ldmatrix_x4(al, ad + 64);
#pragma unroll
                for (int ni = 0; ni < 4; ++ni) {
                    const uint32_t* fbh = &bh[ni >> 1][(ni & 1) * 2];
                    const uint32_t* fbl = &bl[ni >> 1][(ni & 1) * 2];
                    mma_16816(acc[mi][ni], ah, fbh);
                    mma_16816(acc[mi][ni], ah, fbl);
                    mma_16816(acc[mi][ni], al, fbh);
                }
            }
        }
    }

    // epilogue (register accumulators -> gmem)
#pragma unroll
    for (int mi = 0; mi < 4; ++mi) {
#pragma unroll
        for (int ni = 0; ni < 4; ++ni) {
            const int row = mBase + wm * 64 + mi * 16 + gg;
            const int col = nBase + wn * 32 + ni * 8 + tig * 2;
            if (EPI == 0) {
                float2 v0 = make_float2(acc[mi][ni][0], acc[mi][ni][1]);
                float2 v1 = make_float2(acc[mi][ni][2], acc[mi][ni][3]);
                *(float2*)(outF + (size_t)row * HID_ + col)       = v0;
                *(float2*)(outF + (size_t)(row + 8) * HID_ + col) = v1;
            } else {
                const float b0 = bias[col], b1 = bias[col + 1];
                float t0 = tanhf(acc[mi][ni][0] + b0);
                float t1 = tanhf(acc[mi][ni][1] + b1);
                float t2 = tanhf(acc[mi][ni][2] + b0);
                float t3 = tanhf(acc[mi][ni][3] + b1);
                __nv_bfloat16 h0 = __float2bfloat16(t0), h1 = __float2bfloat16(t1);
                __nv_bfloat16 h2 = __float2bfloat16(t2), h3 = __float2bfloat16(t3);
                __nv_bfloat16 l0 = __float2bfloat16(t0 - __bfloat162float(h0));
                __nv_bfloat16 l1 = __float2bfloat16(t1 - __bfloat162float(h1));
                __nv_bfloat16 l2 = __float2bfloat16(t2 - __bfloat162float(h2));
                __nv_bfloat16 l3 = __float2bfloat16(t3 - __bfloat162float(h3));
                const size_t o0 = (size_t)row * HID_ + col;
                const size_t o1 = (size_t)(row + 8) * HID_ + col;
                *(__nv_bfloat162*)(outH + o0) = __halves2bfloat162(h0, h1);
                *(__nv_bfloat162*)(outL + o0) = __halves2bfloat162(l0, l1);
                *(__nv_bfloat162*)(outH + o1) = __halves2bfloat162(h2, h3);
                *(__nv_bfloat162*)(outL + o1) = __halves2bfloat162(l2, l3);
            }
        }
    }
}

// ---------------------------------------------------------------------------
// u = mean over T of v_q
// ---------------------------------------------------------------------------
__global__ void k_mean_vq(const float* __restrict__ vq, float* __restrict__ u) {
    int b = blockIdx.x;
    int h = threadIdx.x;
    const float* p = vq + (size_t)b * T_ * HID_ + h;
    float s = 0.f;
#pragma unroll
    for (int t = 0; t < T_; ++t) s += p[(size_t)t * HID_];
    u[b * HID_ + h] = s * (1.0f / T_);
}

// ---------------------------------------------------------------------------
// fp32 -> bf16 hi/lo elementwise split
// ---------------------------------------------------------------------------
__global__ void k_split(const float* __restrict__ x,
                        __nv_bfloat16* __restrict__ h, __nv_bfloat16* __restrict__ l,
                        int n) {
    int i = blockIdx.x * 256 + threadIdx.x;
    if (i < n) {
        float v = x[i];
        __nv_bfloat16 hi = __float2bfloat16(v);
        h[i] = hi;
        l[i] = __float2bfloat16(v - __bfloat162float(hi));
    }
}

// ---------------------------------------------------------------------------
// v_i [B,C,S] -> A1 [B*S, C] bf16 hi/lo (transpose + split), 32x32 smem tiles
// ---------------------------------------------------------------------------
__global__ void k_conv_vi(const float* __restrict__ vi,
                          __nv_bfloat16* __restrict__ h, __nv_bfloat16* __restrict__ l) {
    __shared__ float t[32][33];
    const int b = blockIdx.x, c0 = blockIdx.y * 32, s0 = blockIdx.z * 32;
    const int tx = threadIdx.x, ty = threadIdx.y;
    const float* src = vi + (size_t)b * C_ * S_;
#pragma unroll
    for (int i = 0; i < 4; ++i) {
        int c = c0 + ty + i * 8;
        int s = s0 + tx;
        t[ty + i * 8][tx] = (s < S_) ? src[(size_t)c * S_ + s] : 0.f;
    }
    __syncthreads();
#pragma unroll
    for (int i = 0; i < 4; ++i) {
        int s = s0 + ty + i * 8;
        if (s < S_) {
            int c = c0 + tx;
            float v = t[tx][ty + i * 8];
            __nv_bfloat16 hi = __float2bfloat16(v);
            size_t o = ((size_t)b * S_ + s) * C_ + c;
            h[o] = hi;
            l[o] = __float2bfloat16(v - __bfloat162float(hi));
        }
    }
}

// ---------------------------------------------------------------------------
// vqt = u @ w_u^T + b_u   [128,1024] x [1024,1024]^T — 64 blocks, 2 b each
// ---------------------------------------------------------------------------
__global__ __launch_bounds__(256)
void k_vqt(const float* __restrict__ u, const float* __restrict__ wu,
           const float* __restrict__ bu, float* __restrict__ vqt) {
    __shared__ float us[2][HID_];
    const int b0 = blockIdx.x * 2;
    const int tid = threadIdx.x;
    for (int i = tid; i < 2 * HID_; i += 256)
        us[i >> 10][i & 1023] = u[(size_t)b0 * HID_ + i];
    __syncthreads();
    const int h0 = tid * 4;
    float acc[2][4] = {};
    for (int k = 0; k < HID_; k += 4) {
        float4 u0 = *(const float4*)&us[0][k];
        float4 u1 = *(const float4*)&us[1][k];
#pragma unroll
        for (int j = 0; j < 4; ++j) {
            float4 w = *(const float4*)&wu[(size_t)(h0 + j) * HID_ + k];
            acc[0][j] += u0.x * w.x + u0.y * w.y + u0.z * w.z + u0.w * w.w;
            acc[1][j] += u1.x * w.x + u1.y * w.y + u1.z * w.z + u1.w * w.w;
        }
    }
#pragma unroll
    for (int j = 0; j < 4; ++j) {
        float bb = bu[h0 + j];
        vqt[(size_t)b0 * HID_ + h0 + j]       = acc[0][j] + bb;
        vqt[(size_t)(b0 + 1) * HID_ + h0 + j] = acc[1][j] + bb;
    }
}

// ---------------------------------------------------------------------------
// Fused attention tail (single pass; tanh bounds exp, no max needed):
// u_out = u_in + (sum_s e*vi) / (sum_s e), e = exp(tanh(z + vqt))
// ---------------------------------------------------------------------------
__global__ __launch_bounds__(256)
void k_attn(const float* __restrict__ Z,
            const __nv_bfloat16* __restrict__ vh, const __nv_bfloat16* __restrict__ vl,
            const float* __restrict__ vqt, const float* __restrict__ uin,
            float* __restrict__ uout) {
    const int b = blockIdx.x;
    const int t = threadIdx.x;
    float vq[4], ae[4], av[4];
#pragma unroll
    for (int j = 0; j < 4; ++j) {
        vq[j] = vqt[b * HID_ + t + j * 256];
        ae[j] = 0.f; av[j] = 0.f;
    }
    const float*         zp  = Z  + (size_t)b * S_ * HID_ + t;
    const __nv_bfloat16* vph = vh + (size_t)b * S_ * HID_ + t;
    const __nv_bfloat16* vpl = vl + (size_t)b * S_ * HID_ + t;
    for (int s = 0; s < S_; ++s) {
#pragma unroll
        for (int j = 0; j < 4; ++j) {
            size_t off = (size_t)s * HID_ + j * 256;
            float z = zp[off];
            float v = __bfloat162float(vph[off]) + __bfloat162float(vpl[off]);
            float e = __expf(tanhf(z + vq[j]));
            ae[j] += e;
            av[j] += e * v;
        }
    }
#pragma unroll
    for (int j = 0; j < 4; ++j) {
        int idx = b * HID_ + t + j * 256;
        uout[idx] = uin[idx] + av[j] / ae[j];
    }
}

// ---------------------------------------------------------------------------
// Launch.  Inputs: 0 v_i, 1 v_q, 2 l1_w, 3 l1_b, 4 w_vi0, 5 w_u0, 6 b_u0,
//                  7 w_vi1, 8 w_u1, 9 b_u1
// ---------------------------------------------------------------------------
extern "C" void kernel_launch(void* const* d_in, const int* in_sizes, int n_in,
                              void* d_out, int out_size) {
    const float* v_i  = (const float*)d_in[0];
    const float* v_q  = (const float*)d_in[1];
    const float* l1_w = (const float*)d_in[2];
    const float* l1_b = (const float*)d_in[3];
    const float* w_vi0= (const float*)d_in[4];
    const float* w_u0 = (const float*)d_in[5];
    const float* b_u0 = (const float*)d_in[6];
    const float* w_vi1= (const float*)d_in[7];
    const float* w_u1 = (const float*)d_in[8];
    const float* b_u1 = (const float*)d_in[9];
    float* out = (float*)d_out;

    __nv_bfloat16 *p_a1h, *p_a1l, *p_vih, *p_vil, *p_l1wh, *p_l1wl;
    __nv_bfloat16 *p_w0h, *p_w0l, *p_w1h, *p_w1l;
    float *p_z, *p_u0, *p_u1, *p_vqt;
    cudaGetSymbolAddress((void**)&p_a1h,  g_a1h);
    cudaGetSymbolAddress((void**)&p_a1l,  g_a1l);
    cudaGetSymbolAddress((void**)&p_vih,  g_vih);
    cudaGetSymbolAddress((void**)&p_vil,  g_vil);
    cudaGetSymbolAddress((void**)&p_l1wh, g_l1wh);
    cudaGetSymbolAddress((void**)&p_l1wl, g_l1wl);
    cudaGetSymbolAddress((void**)&p_w0h,  g_w0h);
    cudaGetSymbolAddress((void**)&p_w0l,  g_w0l);
    cudaGetSymbolAddress((void**)&p_w1h,  g_w1h);
    cudaGetSymbolAddress((void**)&p_w1l,  g_w1l);
    cudaGetSymbolAddress((void**)&p_z,    g_z);
    cudaGetSymbolAddress((void**)&p_u0,   g_u0);
    cudaGetSymbolAddress((void**)&p_u1,   g_u1);
    cudaGetSymbolAddress((void**)&p_vqt,  g_vqt);

    cudaFuncSetAttribute(k_mma_gemm<0>, cudaFuncAttributeMaxDynamicSharedMemorySize, SMEM_DYN);
    cudaFuncSetAttribute(k_mma_gemm<1>, cudaFuncAttributeMaxDynamicSharedMemorySize, SMEM_DYN);

    const dim3 gGemm(HID_ / 128, M_ / 128);   // x = n-tile (8, fast) -> A tiles L2-shared

    // u0 = mean_t v_q
    k_mean_vq<<<B_, HID_>>>(v_q, p_u0);

    // bf16 hi/lo conversions
    k_split<<<(HID_ * C_ + 255) / 256, 256>>>(l1_w, p_l1wh, p_l1wl, HID_ * C_);
    k_split<<<(HID_ * HID_ + 255) / 256, 256>>>(w_vi0, p_w0h, p_w0l, HID_ * HID_);
    k_split<<<(HID_ * HID_ + 255) / 256, 256>>>(w_vi1, p_w1h, p_w1l, HID_ * HID_);
    {
        dim3 g(B_, C_ / 32, (S_ + 31) / 32);
        k_conv_vi<<<g, dim3(32, 8)>>>(v_i, p_a1h, p_a1l);
    }

    // GEMM1: vi = tanh(A1 @ l1_w^T + l1_b) -> bf16 hi/lo
    k_mma_gemm<1><<<gGemm, 256, SMEM_DYN>>>(p_a1h, p_a1l, p_l1wh, p_l1wl,
                                            l1_b, nullptr, p_vih, p_vil, C_, C_ / 32);

    // hop 0
    k_mma_gemm<0><<<gGemm, 256, SMEM_DYN>>>(p_vih, p_vil, p_w0h, p_w0l,
                                            nullptr, p_z, nullptr, nullptr, HID_, HID_ / 32);
    k_vqt<<<B_ / 2, 256>>>(p_u0, w_u0, b_u0, p_vqt);
    k_attn<<<B_, 256>>>(p_z, p_vih, p_vil, p_vqt, p_u0, p_u1);

    // hop 1
    k_mma_gemm<0><<<gGemm, 256, SMEM_DYN>>>(p_vih, p_vil, p_w1h, p_w1l,
                                            nullptr, p_z, nullptr, nullptr, HID_, HID_ / 32);
    k_vqt<<<B_ / 2, 256>>>(p_u1, w_u1, b_u1, p_vqt);
    k_attn<<<B_, 256>>>(p_z, p_vih, p_vil, p_vqt, p_u1, out);
}

// round 10
// speedup vs baseline: 2.2082x; 1.0125x over previous
#include <cuda_runtime.h>
#include <cuda_bf16.h>
#include <math.h>
#include <cstdint>

// Problem constants
#define B_    128
#define C_    2048
#define S_    196          // H*W = 14*14
#define HID_  1024
#define T_    20
#define M_    (B_*S_)      // 25088

// ---------------------------------------------------------------------------
// Scratch (allocation-free rule: __device__ globals)
// ---------------------------------------------------------------------------
__device__ __nv_bfloat16 g_a1h[(size_t)M_*C_];    // v_i transposed, bf16 hi  [M,2048]
__device__ __nv_bfloat16 g_a1l[(size_t)M_*C_];    // v_i transposed, bf16 lo
__device__ __nv_bfloat16 g_vih[(size_t)M_*HID_];  // vi = tanh(l1), bf16 hi   [M,1024]
__device__ __nv_bfloat16 g_vil[(size_t)M_*HID_];  // vi lo
__device__ float         g_z  [(size_t)M_*2*HID_];// z0|z1 concatenated [M,2048]
__device__ __nv_bfloat16 g_l1wh[(size_t)HID_*C_];
__device__ __nv_bfloat16 g_l1wl[(size_t)HID_*C_];
__device__ __nv_bfloat16 g_wch[(size_t)2*HID_*HID_];  // w0|w1 rows 0-1023|1024-2047, hi
__device__ __nv_bfloat16 g_wcl[(size_t)2*HID_*HID_];  // lo
__device__ float g_u0 [B_*HID_];
__device__ float g_u1 [B_*HID_];
__device__ float g_vqt[B_*HID_];

// ---------------------------------------------------------------------------
// Portable (non-arch-specific) PTX helpers: ldmatrix / mma.sync / cp.async
// ---------------------------------------------------------------------------
__device__ __forceinline__ uint32_t smem_to_u32(const void* p) {
    uint32_t a;
    asm("{ .reg .u64 tmp; cvta.to.shared.u64 tmp, %1; cvt.u32.u64 %0, tmp; }"
        : "=r"(a) : "l"(p));
    return a;
}
__device__ __forceinline__ void ldmatrix_x4(uint32_t* r, uint32_t addr) {
    asm volatile("ldmatrix.sync.aligned.m8n8.x4.shared.b16 {%0,%1,%2,%3}, [%4];"
        : "=r"(r[0]), "=r"(r[1]), "=r"(r[2]), "=r"(r[3]) : "r"(addr));
}
__device__ __forceinline__ void mma_16816(float* d, const uint32_t* a, const uint32_t* b) {
    asm volatile(
        "mma.sync.aligned.m16n8k16.row.col.f32.bf16.bf16.f32 "
        "{%0,%1,%2,%3}, {%4,%5,%6,%7}, {%8,%9}, {%0,%1,%2,%3};"
        : "+f"(d[0]), "+f"(d[1]), "+f"(d[2]), "+f"(d[3])
        : "r"(a[0]), "r"(a[1]), "r"(a[2]), "r"(a[3]), "r"(b[0]), "r"(b[1]));
}
__device__ __forceinline__ void ldgsts16(uint32_t dst, const void* src) {
    asm volatile("cp.async.cg.shared.global [%0], [%1], 16;" :: "r"(dst), "l"(src) : "memory");
}
#define CP_COMMIT() asm volatile("cp.async.commit_group;" ::: "memory")
#define CP_WAIT1()  asm volatile("cp.async.wait_group 1;" ::: "memory")

// ---------------------------------------------------------------------------
// HMMA GEMM: C[M,N] = A[M,K] @ B[N,K]^T, A/B as bf16 hi/lo pairs,
// 3-term product (AhBh + AhBl + AlBh), fp32 accumulators in registers.
// CTA tile 128x128, K-chunk 32, 8 warps (2x4, 64x32 warp tiles),
// 3-stage cp.async pipeline (prefetch-first), 2 CTAs per SM.
// SMEM per stage: A_pair[128][144B] (0-63=hi, 64-127=lo, 16B pad) then B_pair.
// 144B = 16*9 -> (9r+c)%8=(r+c)%8: conflict-free ldmatrix + cp.async.
// EPI=0: fp32 out (ld=ldo).  EPI=1: tanh(C+bias) -> bf16 hi/lo (ld=HID_).
// ---------------------------------------------------------------------------
#define ROW_B    144
#define APAIR_B  (128*ROW_B)       // 18432
#define STAGE_B  (2*APAIR_B)       // 36864
#define SMEM_DYN (3*STAGE_B)       // 110592 (x2 CTAs = 216KB <= 228KB)

template<int EPI>
__global__ __launch_bounds__(256, 2)
void k_mma_gemm(const __nv_bfloat16* __restrict__ Ah, const __nv_bfloat16* __restrict__ Al,
                const __nv_bfloat16* __restrict__ Bh, const __nv_bfloat16* __restrict__ Bl,
                const float* __restrict__ bias,
                float* __restrict__ outF,
                __nv_bfloat16* __restrict__ outH, __nv_bfloat16* __restrict__ outL,
                int K, int NK, int ldo)
{
    extern __shared__ char sm[];
    const uint32_t sbase = smem_to_u32(sm);
    const int tid  = threadIdx.x;
    const int wid  = tid >> 5, lane = tid & 31;
    const int wm   = wid >> 2, wn = wid & 3;            // warp grid 2x4
    const int gg   = lane >> 2, tig = lane & 3;
    const int nBase = blockIdx.x * 128;
    const int mBase = blockIdx.y * 128;

    // loader decomposition: gidx = tid + i*256; cc = tid&7 loop-invariant.
    const int cc   = tid & 7;            // 0-3 -> hi chunk, 4-7 -> lo chunk
    const int seg  = cc & 3;             // 16B segment within 64B chunk
    const int lrow = tid >> 3;           // 0..31
    const __nv_bfloat16* srcA = (cc < 4) ? Ah : Al;
    const __nv_bfloat16* srcB = (cc < 4) ? Bh : Bl;

    // ldmatrix thread-address components
    const int a_row  = wm * 64 + ((lane >> 3) & 1) * 8 + (lane & 7);  // + mi*16
    const int a_col  = (lane >> 4) * 8;                               // + k0
    const int b_row  = wn * 32 + (lane >> 4) * 8 + (lane & 7);        // + nb*16
    const int b_col  = ((lane >> 3) & 1) * 8;                         // + k0

    float acc[4][4][4];
#pragma unroll
    for (int mi = 0; mi < 4; ++mi)
#pragma unroll
        for (int ni = 0; ni < 4; ++ni)
#pragma unroll
            for (int c = 0; c < 4; ++c) acc[mi][ni][c] = 0.f;

    auto load_stage = [&](int st, int kt) {
        const int koff = kt * 32 + seg * 8;
        const uint32_t db = sbase + st * STAGE_B + cc * 16;
#pragma unroll
        for (int i = 0; i < 4; ++i) {
            const int row = lrow + i * 32;
            ldgsts16(db + row * ROW_B,           srcA + (size_t)(mBase + row) * K + koff);
            ldgsts16(db + APAIR_B + row * ROW_B, srcB + (size_t)(nBase + row) * K + koff);
        }
    };

    load_stage(0, 0); CP_COMMIT();
    load_stage(1, 1); CP_COMMIT();

    for (int kt = 0; kt < NK; ++kt) {
        const int st = kt % 3;
        CP_WAIT1();                       // chunk kt resident
        __syncthreads();

        // prefetch FIRST so cp.async overlaps the MMA block below.
        if (kt + 2 < NK) load_stage((kt + 2) % 3, kt + 2);
        CP_COMMIT();                      // uniform group count per iteration

        const uint32_t stb = sbase + st * STAGE_B;
#pragma unroll
        for (int half = 0; half < 2; ++half) {
            const int k0 = half * 16;
            uint32_t bh[2][4], bl[2][4];
#pragma unroll
            for (int nb = 0; nb < 2; ++nb) {
                const uint32_t bd = stb + APAIR_B
                    + (uint32_t)(b_row + nb * 16) * ROW_B + (k0 + b_col) * 2;
                ldmatrix_x4(bh[nb], bd);
                ldmatrix_x4(bl[nb], bd + 64);
            }
#pragma unroll
            for (int mi = 0; mi < 4; ++mi) {
                uint32_t ah[4], al[4];
                const uint32_t ad = stb
                    + (uint32_t)(a_row + mi * 16) * ROW_B + (k0 + a_col) * 2;
                ldmatrix_x4(ah, ad);
                ldmatrix_x4(al, ad + 64);
#pragma unroll
                for (int ni = 0; ni < 4; ++ni) {
                    const uint32_t* fbh = &bh[ni >> 1][(ni & 1) * 2];
                    const uint32_t* fbl = &bl[ni >> 1][(ni & 1) * 2];
                    mma_16816(acc[mi][ni], ah, fbh);
                    mma_16816(acc[mi][ni], ah, fbl);
                    mma_16816(acc[mi][ni], al, fbh);
                }
            }
        }
    }

    // epilogue (register accumulators -> gmem)
#pragma unroll
    for (int mi = 0; mi < 4; ++mi) {
#pragma unroll
        for (int ni = 0; ni < 4; ++ni) {
            const int row = mBase + wm * 64 + mi * 16 + gg;
            const int col = nBase + wn * 32 + ni * 8 + tig * 2;
            if (EPI == 0) {
                float2 v0 = make_float2(acc[mi][ni][0], acc[mi][ni][1]);
                float2 v1 = make_float2(acc[mi][ni][2], acc[mi][ni][3]);
                *(float2*)(outF + (size_t)row * ldo + col)       = v0;
                *(float2*)(outF + (size_t)(row + 8) * ldo + col) = v1;
            } else {
                const float b0 = bias[col], b1 = bias[col + 1];
                float t0 = tanhf(acc[mi][ni][0] + b0);
                float t1 = tanhf(acc[mi][ni][1] + b1);
                float t2 = tanhf(acc[mi][ni][2] + b0);
                float t3 = tanhf(acc[mi][ni][3] + b1);
                __nv_bfloat16 h0 = __float2bfloat16(t0), h1 = __float2bfloat16(t1);
                __nv_bfloat16 h2 = __float2bfloat16(t2), h3 = __float2bfloat16(t3);
                __nv_bfloat16 l0 = __float2bfloat16(t0 - __bfloat162float(h0));
                __nv_bfloat16 l1 = __float2bfloat16(t1 - __bfloat162float(h1));
                __nv_bfloat16 l2 = __float2bfloat16(t2 - __bfloat162float(h2));
                __nv_bfloat16 l3 = __float2bfloat16(t3 - __bfloat162float(h3));
                const size_t o0 = (size_t)row * HID_ + col;
                const size_t o1 = (size_t)(row + 8) * HID_ + col;
                *(__nv_bfloat162*)(outH + o0) = __halves2bfloat162(h0, h1);
                *(__nv_bfloat162*)(outL + o0) = __halves2bfloat162(l0, l1);
                *(__nv_bfloat162*)(outH + o1) = __halves2bfloat162(h2, h3);
                *(__nv_bfloat162*)(outL + o1) = __halves2bfloat162(l2, l3);
            }
        }
    }
}

// ---------------------------------------------------------------------------
// u = mean over T of v_q
// ---------------------------------------------------------------------------
__global__ void k_mean_vq(const float* __restrict__ vq, float* __restrict__ u) {
    int b = blockIdx.x;
    int h = threadIdx.x;
    const float* p = vq + (size_t)b * T_ * HID_ + h;
    float s = 0.f;
#pragma unroll
    for (int t = 0; t < T_; ++t) s += p[(size_t)t * HID_];
    u[b * HID_ + h] = s * (1.0f / T_);
}

// ---------------------------------------------------------------------------
// fp32 -> bf16 hi/lo elementwise split (single source)
// ---------------------------------------------------------------------------
__global__ void k_split(const float* __restrict__ x,
                        __nv_bfloat16* __restrict__ h, __nv_bfloat16* __restrict__ l,
                        int n) {
    int i = blockIdx.x * 256 + threadIdx.x;
    if (i < n) {
        float v = x[i];
        __nv_bfloat16 hi = __float2bfloat16(v);
        h[i] = hi;
        l[i] = __float2bfloat16(v - __bfloat162float(hi));
    }
}

// two sources concatenated (w0 rows then w1 rows)
__global__ void k_split2(const float* __restrict__ x0, const float* __restrict__ x1,
                         __nv_bfloat16* __restrict__ h, __nv_bfloat16* __restrict__ l,
                         int half) {
    int i = blockIdx.x * 256 + threadIdx.x;
    if (i < 2 * half) {
        float v = (i < half) ? x0[i] : x1[i - half];
        __nv_bfloat16 hi = __float2bfloat16(v);
        h[i] = hi;
        l[i] = __float2bfloat16(v - __bfloat162float(hi));
    }
}

// ---------------------------------------------------------------------------
// v_i [B,C,S] -> A1 [B*S, C] bf16 hi/lo (transpose + split), 32x32 smem tiles
// ---------------------------------------------------------------------------
__global__ void k_conv_vi(const float* __restrict__ vi,
                          __nv_bfloat16* __restrict__ h, __nv_bfloat16* __restrict__ l) {
    __shared__ float t[32][33];
    const int b = blockIdx.x, c0 = blockIdx.y * 32, s0 = blockIdx.z * 32;
    const int tx = threadIdx.x, ty = threadIdx.y;
    const float* src = vi + (size_t)b * C_ * S_;
#pragma unroll
    for (int i = 0; i < 4; ++i) {
        int c = c0 + ty + i * 8;
        int s = s0 + tx;
        t[ty + i * 8][tx] = (s < S_) ? src[(size_t)c * S_ + s] : 0.f;
    }
    __syncthreads();
#pragma unroll
    for (int i = 0; i < 4; ++i) {
        int s = s0 + ty + i * 8;
        if (s < S_) {
            int c = c0 + tx;
            float v = t[tx][ty + i * 8];
            __nv_bfloat16 hi = __float2bfloat16(v);
            size_t o = ((size_t)b * S_ + s) * C_ + c;
            h[o] = hi;
            l[o] = __float2bfloat16(v - __bfloat162float(hi));
        }
    }
}

// ---------------------------------------------------------------------------
// vqt = u @ w_u^T + b_u   [128,1024] x [1024,1024]^T — 64 blocks, 2 b each
// ---------------------------------------------------------------------------
__global__ __launch_bounds__(256)
void k_vqt(const float* __restrict__ u, const float* __restrict__ wu,
           const float* __restrict__ bu, float* __restrict__ vqt) {
    __shared__ float us[2][HID_];
    const int b0 = blockIdx.x * 2;
    const int tid = threadIdx.x;
    for (int i = tid; i < 2 * HID_; i += 256)
        us[i >> 10][i & 1023] = u[(size_t)b0 * HID_ + i];
    __syncthreads();
    const int h0 = tid * 4;
    float acc[2][4] = {};
    for (int k = 0; k < HID_; k += 4) {
        float4 u0 = *(const float4*)&us[0][k];
        float4 u1 = *(const float4*)&us[1][k];
#pragma unroll
        for (int j = 0; j < 4; ++j) {
            float4 w = *(const float4*)&wu[(size_t)(h0 + j) * HID_ + k];
            acc[0][j] += u0.x * w.x + u0.y * w.y + u0.z * w.z + u0.w * w.w;
            acc[1][j] += u1.x * w.x + u1.y * w.y + u1.z * w.z + u1.w * w.w;
        }
    }
#pragma unroll
    for (int j = 0; j < 4; ++j) {
        float bb = bu[h0 + j];
        vqt[(size_t)b0 * HID_ + h0 + j]       = acc[0][j] + bb;
        vqt[(size_t)(b0 + 1) * HID_ + h0 + j] = acc[1][j] + bb;
    }
}

// ---------------------------------------------------------------------------
// Fused attention tail (single pass; tanh bounds exp, no max needed):
// u_out = u_in + (sum_s e*vi) / (sum_s e), e = exp(tanh(z + vqt))
// Z has leading dim 2*HID_ (z0|z1 concatenated); caller passes hop offset.
// ---------------------------------------------------------------------------
__global__ __launch_bounds__(256)
void k_attn(const float* __restrict__ Z,
            const __nv_bfloat16* __restrict__ vh, const __nv_bfloat16* __restrict__ vl,
            const float* __restrict__ vqt, const float* __restrict__ uin,
            float* __restrict__ uout) {
    const int b = blockIdx.x;
    const int t = threadIdx.x;
    float vq[4], ae[4], av[4];
#pragma unroll
    for (int j = 0; j < 4; ++j) {
        vq[j] = vqt[b * HID_ + t + j * 256];
        ae[j] = 0.f; av[j] = 0.f;
    }
    const float*         zp  = Z  + (size_t)b * S_ * (2 * HID_) + t;
    const __nv_bfloat16* vph = vh + (size_t)b * S_ * HID_ + t;
    const __nv_bfloat16* vpl = vl + (size_t)b * S_ * HID_ + t;
    for (int s = 0; s < S_; ++s) {
#pragma unroll
        for (int j = 0; j < 4; ++j) {
            float z = zp[(size_t)s * (2 * HID_) + j * 256];
            size_t off = (size_t)s * HID_ + j * 256;
            float v = __bfloat162float(vph[off]) + __bfloat162float(vpl[off]);
            float e = __expf(tanhf(z + vq[j]));
            ae[j] += e;
            av[j] += e * v;
        }
    }
#pragma unroll
    for (int j = 0; j < 4; ++j) {
        int idx = b * HID_ + t + j * 256;
        uout[idx] = uin[idx] + av[j] / ae[j];
    }
}

// ---------------------------------------------------------------------------
// Launch.  Inputs: 0 v_i, 1 v_q, 2 l1_w, 3 l1_b, 4 w_vi0, 5 w_u0, 6 b_u0,
//                  7 w_vi1, 8 w_u1, 9 b_u1
// Order chosen so launch #6 (1-based) is the merged hop GEMM -> ncu -s 5 -c 1
// should capture it.
// ---------------------------------------------------------------------------
extern "C" void kernel_launch(void* const* d_in, const int* in_sizes, int n_in,
                              void* d_out, int out_size) {
    const float* v_i  = (const float*)d_in[0];
    const float* v_q  = (const float*)d_in[1];
    const float* l1_w = (const float*)d_in[2];
    const float* l1_b = (const float*)d_in[3];
    const float* w_vi0= (const float*)d_in[4];
    const float* w_u0 = (const float*)d_in[5];
    const float* b_u0 = (const float*)d_in[6];
    const float* w_vi1= (const float*)d_in[7];
    const float* w_u1 = (const float*)d_in[8];
    const float* b_u1 = (const float*)d_in[9];
    float* out = (float*)d_out;

    __nv_bfloat16 *p_a1h, *p_a1l, *p_vih, *p_vil, *p_l1wh, *p_l1wl, *p_wch, *p_wcl;
    float *p_z, *p_u0, *p_u1, *p_vqt;
    cudaGetSymbolAddress((void**)&p_a1h,  g_a1h);
    cudaGetSymbolAddress((void**)&p_a1l,  g_a1l);
    cudaGetSymbolAddress((void**)&p_vih,  g_vih);
    cudaGetSymbolAddress((void**)&p_vil,  g_vil);
    cudaGetSymbolAddress((void**)&p_l1wh, g_l1wh);
    cudaGetSymbolAddress((void**)&p_l1wl, g_l1wl);
    cudaGetSymbolAddress((void**)&p_wch,  g_wch);
    cudaGetSymbolAddress((void**)&p_wcl,  g_wcl);
    cudaGetSymbolAddress((void**)&p_z,    g_z);
    cudaGetSymbolAddress((void**)&p_u0,   g_u0);
    cudaGetSymbolAddress((void**)&p_u1,   g_u1);
    cudaGetSymbolAddress((void**)&p_vqt,  g_vqt);

    cudaFuncSetAttribute(k_mma_gemm<0>, cudaFuncAttributeMaxDynamicSharedMemorySize, SMEM_DYN);
    cudaFuncSetAttribute(k_mma_gemm<1>, cudaFuncAttributeMaxDynamicSharedMemorySize, SMEM_DYN);

    // 1: v_i transpose+split
    {
        dim3 g(B_, C_ / 32, (S_ + 31) / 32);
        k_conv_vi<<<g, dim3(32, 8)>>>(v_i, p_a1h, p_a1l);
    }
    // 2: l1_w split
    k_split<<<(HID_ * C_ + 255) / 256, 256>>>(l1_w, p_l1wh, p_l1wl, HID_ * C_);
    // 3: GEMM1 vi = tanh(A1 @ l1_w^T + l1_b) -> bf16 hi/lo
    {
        dim3 g(HID_ / 128, M_ / 128);
        k_mma_gemm<1><<<g, 256, SMEM_DYN>>>(p_a1h, p_a1l, p_l1wh, p_l1wl,
                                            l1_b, nullptr, p_vih, p_vil,
                                            C_, C_ / 32, HID_);
    }
    // 4: w0|w1 concat split
    k_split2<<<(2 * HID_ * HID_ + 255) / 256, 256>>>(w_vi0, w_vi1, p_wch, p_wcl,
                                                     HID_ * HID_);
    // 5: u0 = mean_t v_q
    k_mean_vq<<<B_, HID_>>>(v_q, p_u0);
    // 6: merged hop GEMM  z0|z1 = vi @ [w0|w1]^T   [M, 2048]
    {
        dim3 g(2 * HID_ / 128, M_ / 128);   // 16 x 196
        k_mma_gemm<0><<<g, 256, SMEM_DYN>>>(p_vih, p_vil, p_wch, p_wcl,
                                            nullptr, p_z, nullptr, nullptr,
                                            HID_, HID_ / 32, 2 * HID_);
    }
    // 7-10: attention chain
    k_vqt<<<B_ / 2, 256>>>(p_u0, w_u0, b_u0, p_vqt);
    k_attn<<<B_, 256>>>(p_z,         p_vih, p_vil, p_vqt, p_u0, p_u1);
    k_vqt<<<B_ / 2, 256>>>(p_u1, w_u1, b_u1, p_vqt);
    k_attn<<<B_, 256>>>(p_z + HID_,  p_vih, p_vil, p_vqt, p_u1, out);
}

// round 11
// speedup vs baseline: 2.6818x; 1.2145x over previous
#include <cuda_runtime.h>
#include <cuda_fp16.h>
#include <math.h>
#include <cstdint>

// Problem constants
#define B_    128
#define C_    2048
#define S_    196          // H*W = 14*14
#define HID_  1024
#define T_    20
#define M_    (B_*S_)      // 25088

// ---------------------------------------------------------------------------
// Scratch (allocation-free rule: __device__ globals)
// A-side operands are fp16 hi/lo pairs; B-side (weights) fp16 hi only.
// ---------------------------------------------------------------------------
__device__ __half g_a1h[(size_t)M_*C_];    // v_i transposed, fp16 hi  [M,2048]
__device__ __half g_a1l[(size_t)M_*C_];    // lo
__device__ __half g_vih[(size_t)M_*HID_];  // vi = tanh(l1), fp16 hi   [M,1024]
__device__ __half g_vil[(size_t)M_*HID_];  // lo
__device__ float  g_z  [(size_t)M_*2*HID_];// z0|z1 concatenated [M,2048]
__device__ __half g_l1w[(size_t)HID_*C_];  // l1_w fp16 (hi only)
__device__ __half g_wc [(size_t)2*HID_*HID_]; // w0|w1 fp16 (hi only)
__device__ float g_u0 [B_*HID_];
__device__ float g_u1 [B_*HID_];
__device__ float g_vqt[B_*HID_];

// ---------------------------------------------------------------------------
// Portable PTX helpers: ldmatrix / mma.sync / cp.async
// ---------------------------------------------------------------------------
__device__ __forceinline__ uint32_t smem_to_u32(const void* p) {
    uint32_t a;
    asm("{ .reg .u64 tmp; cvta.to.shared.u64 tmp, %1; cvt.u32.u64 %0, tmp; }"
        : "=r"(a) : "l"(p));
    return a;
}
__device__ __forceinline__ void ldmatrix_x4(uint32_t* r, uint32_t addr) {
    asm volatile("ldmatrix.sync.aligned.m8n8.x4.shared.b16 {%0,%1,%2,%3}, [%4];"
        : "=r"(r[0]), "=r"(r[1]), "=r"(r[2]), "=r"(r[3]) : "r"(addr));
}
__device__ __forceinline__ void mma_16816(float* d, const uint32_t* a, const uint32_t* b) {
    asm volatile(
        "mma.sync.aligned.m16n8k16.row.col.f32.f16.f16.f32 "
        "{%0,%1,%2,%3}, {%4,%5,%6,%7}, {%8,%9}, {%0,%1,%2,%3};"
        : "+f"(d[0]), "+f"(d[1]), "+f"(d[2]), "+f"(d[3])
        : "r"(a[0]), "r"(a[1]), "r"(a[2]), "r"(a[3]), "r"(b[0]), "r"(b[1]));
}
__device__ __forceinline__ void ldgsts16(uint32_t dst, const void* src) {
    asm volatile("cp.async.cg.shared.global [%0], [%1], 16;" :: "r"(dst), "l"(src) : "memory");
}
#define CP_COMMIT() asm volatile("cp.async.commit_group;" ::: "memory")
#define CP_WAIT1()  asm volatile("cp.async.wait_group 1;" ::: "memory")

// ---------------------------------------------------------------------------
// HMMA GEMM: C[M,N] = A[M,K] @ B[N,K]^T
// A as fp16 hi/lo pair (22-bit effective), B as fp16 hi only.
// 2-term product per tile: AhB + AlB, fp32 register accumulators.
// CTA tile 128x128, K-chunk 32, 8 warps (2x4, 64x32 warp tiles),
// 3-stage cp.async pipeline (prefetch-first), 2 CTAs per SM.
// SMEM per stage: A_pair[128][144B] (0-63=hi, 64-127=lo, 16B pad),
// then B[128][80B] (0-63=data, 16B pad).
// 144B=16*9, 80B=16*5: odd multiples of 16 -> (row+col)-preserving bank map,
// conflict-free ldmatrix + cp.async.
// EPI=0: fp32 out (ld=ldo).  EPI=1: tanh(C+bias) -> fp16 hi/lo (ld=HID_).
// ---------------------------------------------------------------------------
#define ROW_A    144
#define ROW_BB   80
#define BOFF_B   (128*ROW_A)             // 18432
#define STAGE_B  (BOFF_B + 128*ROW_BB)   // 28672
#define SMEM_DYN (3*STAGE_B)             // 86016 (x2 CTAs = 168KB <= 228KB)

template<int EPI>
__global__ __launch_bounds__(256, 2)
void k_mma_gemm(const __half* __restrict__ Ah, const __half* __restrict__ Al,
                const __half* __restrict__ Bh,
                const float* __restrict__ bias,
                float* __restrict__ outF,
                __half* __restrict__ outH, __half* __restrict__ outL,
                int K, int NK, int ldo)
{
    extern __shared__ char sm[];
    const uint32_t sbase = smem_to_u32(sm);
    const int tid  = threadIdx.x;
    const int wid  = tid >> 5, lane = tid & 31;
    const int wm   = wid >> 2, wn = wid & 3;            // warp grid 2x4
    const int gg   = lane >> 2, tig = lane & 3;
    const int nBase = blockIdx.x * 128;
    const int mBase = blockIdx.y * 128;

    // A loader: cc = tid&7 (0-3 hi seg / 4-7 lo seg), row = tid>>3 (+32 x4)
    const int cc   = tid & 7;
    const int segA = cc & 3;
    const int lrowA = tid >> 3;
    const __half* srcA = (cc < 4) ? Ah : Al;
    // B loader: cb = tid&3 seg, rowb = tid>>2 (+64 x2)
    const int cb    = tid & 3;
    const int lrowB = tid >> 2;

    // ldmatrix thread-address components
    const int a_row  = wm * 64 + ((lane >> 3) & 1) * 8 + (lane & 7);  // + mi*16
    const int a_col  = (lane >> 4) * 8;                               // + k0
    const int b_row  = wn * 32 + (lane >> 4) * 8 + (lane & 7);        // + nb*16
    const int b_col  = ((lane >> 3) & 1) * 8;                         // + k0

    float acc[4][4][4];
#pragma unroll
    for (int mi = 0; mi < 4; ++mi)
#pragma unroll
        for (int ni = 0; ni < 4; ++ni)
#pragma unroll
            for (int c = 0; c < 4; ++c) acc[mi][ni][c] = 0.f;

    auto load_stage = [&](int st, int kt) {
        const uint32_t stb = sbase + st * STAGE_B;
        {   // A: 1024 16B-chunks, 4 per thread
            const int koff = kt * 32 + segA * 8;
            const uint32_t db = stb + cc * 16;
#pragma unroll
            for (int i = 0; i < 4; ++i) {
                const int row = lrowA + i * 32;
                ldgsts16(db + row * ROW_A, srcA + (size_t)(mBase + row) * K + koff);
            }
        }
        {   // B: 512 16B-chunks, 2 per thread
            const int koff = kt * 32 + cb * 8;
            const uint32_t db = stb + BOFF_B + cb * 16;
#pragma unroll
            for (int i = 0; i < 2; ++i) {
                const int row = lrowB + i * 64;
                ldgsts16(db + row * ROW_BB, Bh + (size_t)(nBase + row) * K + koff);
            }
        }
    };

    load_stage(0, 0); CP_COMMIT();
    load_stage(1, 1); CP_COMMIT();

    for (int kt = 0; kt < NK; ++kt) {
        const int st = kt % 3;
        CP_WAIT1();                       // chunk kt resident
        __syncthreads();

        // prefetch FIRST so cp.async overlaps the MMA block below
        if (kt + 2 < NK) load_stage((kt + 2) % 3, kt + 2);
        CP_COMMIT();                      // uniform group count per iteration

        const uint32_t stb = sbase + st * STAGE_B;
#pragma unroll
        for (int half = 0; half < 2; ++half) {
            const int k0 = half * 16;
            uint32_t bh[2][4];
#pragma unroll
            for (int nb = 0; nb < 2; ++nb) {
                const uint32_t bd = stb + BOFF_B
                    + (uint32_t)(b_row + nb * 16) * ROW_BB + (k0 + b_col) * 2;
                ldmatrix_x4(bh[nb], bd);
            }
#pragma unroll
            for (int mi = 0; mi < 4; ++mi) {
                uint32_t ah[4], al[4];
                const uint32_t ad = stb
                    + (uint32_t)(a_row + mi * 16) * ROW_A + (k0 + a_col) * 2;
                ldmatrix_x4(ah, ad);
                ldmatrix_x4(al, ad + 64);
#pragma unroll
                for (int ni = 0; ni < 4; ++ni) {
                    const uint32_t* fb = &bh[ni >> 1][(ni & 1) * 2];
                    mma_16816(acc[mi][ni], ah, fb);
                    mma_16816(acc[mi][ni], al, fb);
                }
            }
        }
    }

    // epilogue (register accumulators -> gmem)
#pragma unroll
    for (int mi = 0; mi < 4; ++mi) {
#pragma unroll
        for (int ni = 0; ni < 4; ++ni) {
            const int row = mBase + wm * 64 + mi * 16 + gg;
            const int col = nBase + wn * 32 + ni * 8 + tig * 2;
            if (EPI == 0) {
                float2 v0 = make_float2(acc[mi][ni][0], acc[mi][ni][1]);
                float2 v1 = make_float2(acc[mi][ni][2], acc[mi][ni][3]);
                *(float2*)(outF + (size_t)row * ldo + col)       = v0;
                *(float2*)(outF + (size_t)(row + 8) * ldo + col) = v1;
            } else {
                const float b0 = bias[col], b1 = bias[col + 1];
                float t0 = tanhf(acc[mi][ni][0] + b0);
                float t1 = tanhf(acc[mi][ni][1] + b1);
                float t2 = tanhf(acc[mi][ni][2] + b0);
                float t3 = tanhf(acc[mi][ni][3] + b1);
                __half h0 = __float2half_rn(t0), h1 = __float2half_rn(t1);
                __half h2 = __float2half_rn(t2), h3 = __float2half_rn(t3);
                __half l0 = __float2half_rn(t0 - __half2float(h0));
                __half l1 = __float2half_rn(t1 - __half2float(h1));
                __half l2 = __float2half_rn(t2 - __half2float(h2));
                __half l3 = __float2half_rn(t3 - __half2float(h3));
                const size_t o0 = (size_t)row * HID_ + col;
                const size_t o1 = (size_t)(row + 8) * HID_ + col;
                *(__half2*)(outH + o0) = __halves2half2(h0, h1);
                *(__half2*)(outL + o0) = __halves2half2(l0, l1);
                *(__half2*)(outH + o1) = __halves2half2(h2, h3);
                *(__half2*)(outL + o1) = __halves2half2(l2, l3);
            }
        }
    }
}

// ---------------------------------------------------------------------------
// u = mean over T of v_q
// ---------------------------------------------------------------------------
__global__ void k_mean_vq(const float* __restrict__ vq, float* __restrict__ u) {
    int b = blockIdx.x;
    int h = threadIdx.x;
    const float* p = vq + (size_t)b * T_ * HID_ + h;
    float s = 0.f;
#pragma unroll
    for (int t = 0; t < T_; ++t) s += p[(size_t)t * HID_];
    u[b * HID_ + h] = s * (1.0f / T_);
}

// ---------------------------------------------------------------------------
// fp32 -> fp16 (hi only) conversion, single source
// ---------------------------------------------------------------------------
__global__ void k_half(const float* __restrict__ x, __half* __restrict__ h, int n) {
    int i = blockIdx.x * 256 + threadIdx.x;
    if (i < n) h[i] = __float2half_rn(x[i]);
}
// two sources concatenated (w0 rows then w1 rows)
__global__ void k_half2src(const float* __restrict__ x0, const float* __restrict__ x1,
                           __half* __restrict__ h, int half_n) {
    int i = blockIdx.x * 256 + threadIdx.x;
    if (i < 2 * half_n)
        h[i] = __float2half_rn((i < half_n) ? x0[i] : x1[i - half_n]);
}

// ---------------------------------------------------------------------------
// v_i [B,C,S] -> A1 [B*S, C] fp16 hi/lo (transpose + split), 32x32 smem tiles
// ---------------------------------------------------------------------------
__global__ void k_conv_vi(const float* __restrict__ vi,
                          __half* __restrict__ h, __half* __restrict__ l) {
    __shared__ float t[32][33];
    const int b = blockIdx.x, c0 = blockIdx.y * 32, s0 = blockIdx.z * 32;
    const int tx = threadIdx.x, ty = threadIdx.y;
    const float* src = vi + (size_t)b * C_ * S_;
#pragma unroll
    for (int i = 0; i < 4; ++i) {
        int c = c0 + ty + i * 8;
        int s = s0 + tx;
        t[ty + i * 8][tx] = (s < S_) ? src[(size_t)c * S_ + s] : 0.f;
    }
    __syncthreads();
#pragma unroll
    for (int i = 0; i < 4; ++i) {
        int s = s0 + ty + i * 8;
        if (s < S_) {
            int c = c0 + tx;
            float v = t[tx][ty + i * 8];
            __half hi = __float2half_rn(v);
            size_t o = ((size_t)b * S_ + s) * C_ + c;
            h[o] = hi;
            l[o] = __float2half_rn(v - __half2float(hi));
        }
    }
}

// ---------------------------------------------------------------------------
// vqt = u @ w_u^T + b_u   [128,1024] x [1024,1024]^T — 64 blocks, 2 b each
// ---------------------------------------------------------------------------
__global__ __launch_bounds__(256)
void k_vqt(const float* __restrict__ u, const float* __restrict__ wu,
           const float* __restrict__ bu, float* __restrict__ vqt) {
    __shared__ float us[2][HID_];
    const int b0 = blockIdx.x * 2;
    const int tid = threadIdx.x;
    for (int i = tid; i < 2 * HID_; i += 256)
        us[i >> 10][i & 1023] = u[(size_t)b0 * HID_ + i];
    __syncthreads();
    const int h0 = tid * 4;
    float acc[2][4] = {};
    for (int k = 0; k < HID_; k += 4) {
        float4 u0 = *(const float4*)&us[0][k];
        float4 u1 = *(const float4*)&us[1][k];
#pragma unroll
        for (int j = 0; j < 4; ++j) {
            float4 w = *(const float4*)&wu[(size_t)(h0 + j) * HID_ + k];
            acc[0][j] += u0.x * w.x + u0.y * w.y + u0.z * w.z + u0.w * w.w;
            acc[1][j] += u1.x * w.x + u1.y * w.y + u1.z * w.z + u1.w * w.w;
        }
    }
#pragma unroll
    for (int j = 0; j < 4; ++j) {
        float bb = bu[h0 + j];
        vqt[(size_t)b0 * HID_ + h0 + j]       = acc[0][j] + bb;
        vqt[(size_t)(b0 + 1) * HID_ + h0 + j] = acc[1][j] + bb;
    }
}

// ---------------------------------------------------------------------------
// Fused attention tail (single pass; tanh bounds exp, no max needed):
// u_out = u_in + (sum_s e*vi) / (sum_s e), e = exp(tanh(z + vqt))
// Z leading dim 2*HID_ (z0|z1 concatenated); caller passes hop offset.
// ---------------------------------------------------------------------------
__global__ __launch_bounds__(256)
void k_attn(const float* __restrict__ Z,
            const __half* __restrict__ vh, const __half* __restrict__ vl,
            const float* __restrict__ vqt, const float* __restrict__ uin,
            float* __restrict__ uout) {
    const int b = blockIdx.x;
    const int t = threadIdx.x;
    float vq[4], ae[4], av[4];
#pragma unroll
    for (int j = 0; j < 4; ++j) {
        vq[j] = vqt[b * HID_ + t + j * 256];
        ae[j] = 0.f; av[j] = 0.f;
    }
    const float*  zp  = Z  + (size_t)b * S_ * (2 * HID_) + t;
    const __half* vph = vh + (size_t)b * S_ * HID_ + t;
    const __half* vpl = vl + (size_t)b * S_ * HID_ + t;
    for (int s = 0; s < S_; ++s) {
#pragma unroll
        for (int j = 0; j < 4; ++j) {
            float z = zp[(size_t)s * (2 * HID_) + j * 256];
            size_t off = (size_t)s * HID_ + j * 256;
            float v = __half2float(vph[off]) + __half2float(vpl[off]);
            float e = __expf(tanhf(z + vq[j]));
            ae[j] += e;
            av[j] += e * v;
        }
    }
#pragma unroll
    for (int j = 0; j < 4; ++j) {
        int idx = b * HID_ + t + j * 256;
        uout[idx] = uin[idx] + av[j] / ae[j];
    }
}

// ---------------------------------------------------------------------------
// Launch.  Inputs: 0 v_i, 1 v_q, 2 l1_w, 3 l1_b, 4 w_vi0, 5 w_u0, 6 b_u0,
//                  7 w_vi1, 8 w_u1, 9 b_u1
// ---------------------------------------------------------------------------
extern "C" void kernel_launch(void* const* d_in, const int* in_sizes, int n_in,
                              void* d_out, int out_size) {
    const float* v_i  = (const float*)d_in[0];
    const float* v_q  = (const float*)d_in[1];
    const float* l1_w = (const float*)d_in[2];
    const float* l1_b = (const float*)d_in[3];
    const float* w_vi0= (const float*)d_in[4];
    const float* w_u0 = (const float*)d_in[5];
    const float* b_u0 = (const float*)d_in[6];
    const float* w_vi1= (const float*)d_in[7];
    const float* w_u1 = (const float*)d_in[8];
    const float* b_u1 = (const float*)d_in[9];
    float* out = (float*)d_out;

    __half *p_a1h, *p_a1l, *p_vih, *p_vil, *p_l1w, *p_wc;
    float *p_z, *p_u0, *p_u1, *p_vqt;
    cudaGetSymbolAddress((void**)&p_a1h, g_a1h);
    cudaGetSymbolAddress((void**)&p_a1l, g_a1l);
    cudaGetSymbolAddress((void**)&p_vih, g_vih);
    cudaGetSymbolAddress((void**)&p_vil, g_vil);
    cudaGetSymbolAddress((void**)&p_l1w, g_l1w);
    cudaGetSymbolAddress((void**)&p_wc,  g_wc);
    cudaGetSymbolAddress((void**)&p_z,   g_z);
    cudaGetSymbolAddress((void**)&p_u0,  g_u0);
    cudaGetSymbolAddress((void**)&p_u1,  g_u1);
    cudaGetSymbolAddress((void**)&p_vqt, g_vqt);

    cudaFuncSetAttribute(k_mma_gemm<0>, cudaFuncAttributeMaxDynamicSharedMemorySize, SMEM_DYN);
    cudaFuncSetAttribute(k_mma_gemm<1>, cudaFuncAttributeMaxDynamicSharedMemorySize, SMEM_DYN);

    // 1: v_i transpose + fp16 hi/lo split
    {
        dim3 g(B_, C_ / 32, (S_ + 31) / 32);
        k_conv_vi<<<g, dim3(32, 8)>>>(v_i, p_a1h, p_a1l);
    }
    // 2: l1_w -> fp16
    k_half<<<(HID_ * C_ + 255) / 256, 256>>>(l1_w, p_l1w, HID_ * C_);
    // 3: GEMM1 vi = tanh(A1 @ l1_w^T + l1_b) -> fp16 hi/lo
    {
        dim3 g(HID_ / 128, M_ / 128);
        k_mma_gemm<1><<<g, 256, SMEM_DYN>>>(p_a1h, p_a1l, p_l1w,
                                            l1_b, nullptr, p_vih, p_vil,
                                            C_, C_ / 32, HID_);
    }
    // 4: w0|w1 concat -> fp16
    k_half2src<<<(2 * HID_ * HID_ + 255) / 256, 256>>>(w_vi0, w_vi1, p_wc, HID_ * HID_);
    // 5: u0 = mean_t v_q
    k_mean_vq<<<B_, HID_>>>(v_q, p_u0);
    // 6: merged hop GEMM  z0|z1 = vi @ [w0|w1]^T   [M, 2048]
    {
        dim3 g(2 * HID_ / 128, M_ / 128);   // 16 x 196
        k_mma_gemm<0><<<g, 256, SMEM_DYN>>>(p_vih, p_vil, p_wc,
                                            nullptr, p_z, nullptr, nullptr,
                                            HID_, HID_ / 32, 2 * HID_);
    }
    // 7-10: attention chain
    k_vqt<<<B_ / 2, 256>>>(p_u0, w_u0, b_u0, p_vqt);
    k_attn<<<B_, 256>>>(p_z,        p_vih, p_vil, p_vqt, p_u0, p_u1);
    k_vqt<<<B_ / 2, 256>>>(p_u1, w_u1, b_u1, p_vqt);
    k_attn<<<B_, 256>>>(p_z + HID_, p_vih, p_vil, p_vqt, p_u1, out);
}

// round 12
// speedup vs baseline: 4.2099x; 1.5698x over previous
#include <cuda_runtime.h>
#include <cuda_fp16.h>
#include <math.h>
#include <cstdint>

// Problem constants
#define B_    128
#define C_    2048
#define S_    196          // H*W = 14*14
#define HID_  1024
#define T_    20
#define M_    (B_*S_)      // 25088

// ---------------------------------------------------------------------------
// Scratch (allocation-free rule: __device__ globals)
// Pure fp16 operands, fp32 accumulation inside the GEMMs.
// ---------------------------------------------------------------------------
__device__ __half g_a1 [(size_t)M_*C_];      // v_i transposed fp16  [M,2048]
__device__ __half g_vi [(size_t)M_*HID_];    // vi = tanh(l1) fp16   [M,1024]
__device__ __half g_z  [(size_t)M_*2*HID_];  // z0|z1 fp16 [M,2048]
__device__ __half g_l1w[(size_t)HID_*C_];    // l1_w fp16
__device__ __half g_wc [(size_t)2*HID_*HID_];// w0|w1 fp16
__device__ float g_u0 [B_*HID_];
__device__ float g_u1 [B_*HID_];
__device__ float g_vqt[B_*HID_];

// ---------------------------------------------------------------------------
// Portable PTX helpers: ldmatrix / mma.sync / cp.async
// ---------------------------------------------------------------------------
__device__ __forceinline__ uint32_t smem_to_u32(const void* p) {
    uint32_t a;
    asm("{ .reg .u64 tmp; cvta.to.shared.u64 tmp, %1; cvt.u32.u64 %0, tmp; }"
        : "=r"(a) : "l"(p));
    return a;
}
__device__ __forceinline__ void ldmatrix_x4(uint32_t* r, uint32_t addr) {
    asm volatile("ldmatrix.sync.aligned.m8n8.x4.shared.b16 {%0,%1,%2,%3}, [%4];"
        : "=r"(r[0]), "=r"(r[1]), "=r"(r[2]), "=r"(r[3]) : "r"(addr));
}
__device__ __forceinline__ void mma_16816(float* d, const uint32_t* a, const uint32_t* b) {
    asm volatile(
        "mma.sync.aligned.m16n8k16.row.col.f32.f16.f16.f32 "
        "{%0,%1,%2,%3}, {%4,%5,%6,%7}, {%8,%9}, {%0,%1,%2,%3};"
        : "+f"(d[0]), "+f"(d[1]), "+f"(d[2]), "+f"(d[3])
        : "r"(a[0]), "r"(a[1]), "r"(a[2]), "r"(a[3]), "r"(b[0]), "r"(b[1]));
}
__device__ __forceinline__ void ldgsts16(uint32_t dst, const void* src) {
    asm volatile("cp.async.cg.shared.global [%0], [%1], 16;" :: "r"(dst), "l"(src) : "memory");
}
#define CP_COMMIT() asm volatile("cp.async.commit_group;" ::: "memory")
#define CP_WAIT1()  asm volatile("cp.async.wait_group 1;" ::: "memory")

// ---------------------------------------------------------------------------
// fp16 HMMA GEMM: C[M,N] = A[M,K] @ B[N,K]^T, fp32 accum.
// CTA tile 128x128, K-chunk 64, 8 warps (2x4, 64x32 warp tiles),
// 3-stage cp.async pipeline (prefetch-first), 2 CTAs per SM.
// SMEM per stage: A[128][144B] (128B data + 16B pad) then B likewise.
// 144B = 16*9 (odd multiple of 16) -> conflict-free ldmatrix + cp.async.
// EPI=0: fp16 out (ld=ldo).  EPI=1: tanh(C+bias) -> fp16 (ld=HID_).
// ---------------------------------------------------------------------------
#define ROW_T    144
#define BOFF     (128*ROW_T)          // 18432
#define STAGE_B  (2*BOFF)             // 36864
#define SMEM_DYN (3*STAGE_B)          // 110592 (x2 CTAs = 221184 <= 228KB)

template<int EPI>
__global__ __launch_bounds__(256, 2)
void k_mma_gemm(const __half* __restrict__ A, const __half* __restrict__ B,
                const float* __restrict__ bias,
                __half* __restrict__ outZ, __half* __restrict__ outV,
                int K, int NK, int ldo)
{
    extern __shared__ char sm[];
    const uint32_t sbase = smem_to_u32(sm);
    const int tid  = threadIdx.x;
    const int wid  = tid >> 5, lane = tid & 31;
    const int wm   = wid >> 2, wn = wid & 3;            // warp grid 2x4
    const int gg   = lane >> 2, tig = lane & 3;
    const int nBase = blockIdx.x * 128;
    const int mBase = blockIdx.y * 128;

    // loader: 1024 16B chunks per array; 4 per thread per array.
    const int cc   = tid & 7;            // 16B segment within 128B row
    const int lrow = tid >> 3;           // 0..31 (+32 x4)

    // ldmatrix thread-address components
    const int a_row  = wm * 64 + ((lane >> 3) & 1) * 8 + (lane & 7);  // + mi*16
    const int a_col  = (lane >> 4) * 8;                               // + k0
    const int b_row  = wn * 32 + (lane >> 4) * 8 + (lane & 7);        // + nb*16
    const int b_col  = ((lane >> 3) & 1) * 8;                         // + k0

    float acc[4][4][4];
#pragma unroll
    for (int mi = 0; mi < 4; ++mi)
#pragma unroll
        for (int ni = 0; ni < 4; ++ni)
#pragma unroll
            for (int c = 0; c < 4; ++c) acc[mi][ni][c] = 0.f;

    auto load_stage = [&](int st, int kt) {
        const int koff = kt * 64 + cc * 8;
        const uint32_t db = sbase + st * STAGE_B + cc * 16;
#pragma unroll
        for (int i = 0; i < 4; ++i) {
            const int row = lrow + i * 32;
            ldgsts16(db + row * ROW_T,        A + (size_t)(mBase + row) * K + koff);
            ldgsts16(db + BOFF + row * ROW_T, B + (size_t)(nBase + row) * K + koff);
        }
    };

    load_stage(0, 0); CP_COMMIT();
    load_stage(1, 1); CP_COMMIT();

    for (int kt = 0; kt < NK; ++kt) {
        const int st = kt % 3;
        CP_WAIT1();                       // chunk kt resident
        __syncthreads();

        // prefetch FIRST so cp.async overlaps the MMA block below
        if (kt + 2 < NK) load_stage((kt + 2) % 3, kt + 2);
        CP_COMMIT();                      // uniform group count per iteration

        const uint32_t stb = sbase + st * STAGE_B;
#pragma unroll
        for (int half = 0; half < 4; ++half) {
            const int k0 = half * 16;
            uint32_t bh[2][4];
#pragma unroll
            for (int nb = 0; nb < 2; ++nb) {
                const uint32_t bd = stb + BOFF
                    + (uint32_t)(b_row + nb * 16) * ROW_T + (k0 + b_col) * 2;
                ldmatrix_x4(bh[nb], bd);
            }
#pragma unroll
            for (int mi = 0; mi < 4; ++mi) {
                uint32_t ah[4];
                const uint32_t ad = stb
                    + (uint32_t)(a_row + mi * 16) * ROW_T + (k0 + a_col) * 2;
                ldmatrix_x4(ah, ad);
#pragma unroll
                for (int ni = 0; ni < 4; ++ni)
                    mma_16816(acc[mi][ni], ah, &bh[ni >> 1][(ni & 1) * 2]);
            }
        }
    }

    // epilogue (register accumulators -> gmem, fp16)
#pragma unroll
    for (int mi = 0; mi < 4; ++mi) {
#pragma unroll
        for (int ni = 0; ni < 4; ++ni) {
            const int row = mBase + wm * 64 + mi * 16 + gg;
            const int col = nBase + wn * 32 + ni * 8 + tig * 2;
            if (EPI == 0) {
                const size_t o0 = (size_t)row * ldo + col;
                const size_t o1 = (size_t)(row + 8) * ldo + col;
                *(__half2*)(outZ + o0) =
                    __halves2half2(__float2half_rn(acc[mi][ni][0]),
                                   __float2half_rn(acc[mi][ni][1]));
                *(__half2*)(outZ + o1) =
                    __halves2half2(__float2half_rn(acc[mi][ni][2]),
                                   __float2half_rn(acc[mi][ni][3]));
            } else {
                const float b0 = bias[col], b1 = bias[col + 1];
                float t0 = tanhf(acc[mi][ni][0] + b0);
                float t1 = tanhf(acc[mi][ni][1] + b1);
                float t2 = tanhf(acc[mi][ni][2] + b0);
                float t3 = tanhf(acc[mi][ni][3] + b1);
                const size_t o0 = (size_t)row * HID_ + col;
                const size_t o1 = (size_t)(row + 8) * HID_ + col;
                *(__half2*)(outV + o0) =
                    __halves2half2(__float2half_rn(t0), __float2half_rn(t1));
                *(__half2*)(outV + o1) =
                    __halves2half2(__float2half_rn(t2), __float2half_rn(t3));
            }
        }
    }
}

// ---------------------------------------------------------------------------
// u = mean over T of v_q
// ---------------------------------------------------------------------------
__global__ void k_mean_vq(const float* __restrict__ vq, float* __restrict__ u) {
    int b = blockIdx.x;
    int h = threadIdx.x;
    const float* p = vq + (size_t)b * T_ * HID_ + h;
    float s = 0.f;
#pragma unroll
    for (int t = 0; t < T_; ++t) s += p[(size_t)t * HID_];
    u[b * HID_ + h] = s * (1.0f / T_);
}

// ---------------------------------------------------------------------------
// fp32 -> fp16 conversions
// ---------------------------------------------------------------------------
__global__ void k_half(const float* __restrict__ x, __half* __restrict__ h, int n) {
    int i = blockIdx.x * 256 + threadIdx.x;
    if (i < n) h[i] = __float2half_rn(x[i]);
}
__global__ void k_half2src(const float* __restrict__ x0, const float* __restrict__ x1,
                           __half* __restrict__ h, int half_n) {
    int i = blockIdx.x * 256 + threadIdx.x;
    if (i < 2 * half_n)
        h[i] = __float2half_rn((i < half_n) ? x0[i] : x1[i - half_n]);
}

// ---------------------------------------------------------------------------
// v_i [B,C,S] -> A1 [B*S, C] fp16 (transpose), 32x32 smem tiles
// ---------------------------------------------------------------------------
__global__ void k_conv_vi(const float* __restrict__ vi, __half* __restrict__ h) {
    __shared__ float t[32][33];
    const int b = blockIdx.x, c0 = blockIdx.y * 32, s0 = blockIdx.z * 32;
    const int tx = threadIdx.x, ty = threadIdx.y;
    const float* src = vi + (size_t)b * C_ * S_;
#pragma unroll
    for (int i = 0; i < 4; ++i) {
        int c = c0 + ty + i * 8;
        int s = s0 + tx;
        t[ty + i * 8][tx] = (s < S_) ? src[(size_t)c * S_ + s] : 0.f;
    }
    __syncthreads();
#pragma unroll
    for (int i = 0; i < 4; ++i) {
        int s = s0 + ty + i * 8;
        if (s < S_) {
            int c = c0 + tx;
            h[((size_t)b * S_ + s) * C_ + c] = __float2half_rn(t[tx][ty + i * 8]);
        }
    }
}

// ---------------------------------------------------------------------------
// vqt = u @ w_u^T + b_u   [128,1024] x [1024,1024]^T — 64 blocks, 2 b each
// ---------------------------------------------------------------------------
__global__ __launch_bounds__(256)
void k_vqt(const float* __restrict__ u, const float* __restrict__ wu,
           const float* __restrict__ bu, float* __restrict__ vqt) {
    __shared__ float us[2][HID_];
    const int b0 = blockIdx.x * 2;
    const int tid = threadIdx.x;
    for (int i = tid; i < 2 * HID_; i += 256)
        us[i >> 10][i & 1023] = u[(size_t)b0 * HID_ + i];
    __syncthreads();
    const int h0 = tid * 4;
    float acc[2][4] = {};
    for (int k = 0; k < HID_; k += 4) {
        float4 u0 = *(const float4*)&us[0][k];
        float4 u1 = *(const float4*)&us[1][k];
#pragma unroll
        for (int j = 0; j < 4; ++j) {
            float4 w = *(const float4*)&wu[(size_t)(h0 + j) * HID_ + k];
            acc[0][j] += u0.x * w.x + u0.y * w.y + u0.z * w.z + u0.w * w.w;
            acc[1][j] += u1.x * w.x + u1.y * w.y + u1.z * w.z + u1.w * w.w;
        }
    }
#pragma unroll
    for (int j = 0; j < 4; ++j) {
        float bb = bu[h0 + j];
        vqt[(size_t)b0 * HID_ + h0 + j]       = acc[0][j] + bb;
        vqt[(size_t)(b0 + 1) * HID_ + h0 + j] = acc[1][j] + bb;
    }
}

// ---------------------------------------------------------------------------
// Fused attention tail (single pass; tanh bounds exp, no max needed):
// u_out = u_in + (sum_s e*vi) / (sum_s e), e = exp(tanh(z + vqt))
// Z fp16 with leading dim 2*HID_ (z0|z1); caller passes hop offset.
// ---------------------------------------------------------------------------
__global__ __launch_bounds__(256)
void k_attn(const __half* __restrict__ Z, const __half* __restrict__ vh,
            const float* __restrict__ vqt, const float* __restrict__ uin,
            float* __restrict__ uout) {
    const int b = blockIdx.x;
    const int t = threadIdx.x;
    float vq[4], ae[4], av[4];
#pragma unroll
    for (int j = 0; j < 4; ++j) {
        vq[j] = vqt[b * HID_ + t + j * 256];
        ae[j] = 0.f; av[j] = 0.f;
    }
    const __half* zp  = Z  + (size_t)b * S_ * (2 * HID_) + t;
    const __half* vph = vh + (size_t)b * S_ * HID_ + t;
    for (int s = 0; s < S_; ++s) {
#pragma unroll
        for (int j = 0; j < 4; ++j) {
            float z = __half2float(zp[(size_t)s * (2 * HID_) + j * 256]);
            float v = __half2float(vph[(size_t)s * HID_ + j * 256]);
            float e = __expf(tanhf(z + vq[j]));
            ae[j] += e;
            av[j] += e * v;
        }
    }
#pragma unroll
    for (int j = 0; j < 4; ++j) {
        int idx = b * HID_ + t + j * 256;
        uout[idx] = uin[idx] + av[j] / ae[j];
    }
}

// ---------------------------------------------------------------------------
// Launch.  Inputs: 0 v_i, 1 v_q, 2 l1_w, 3 l1_b, 4 w_vi0, 5 w_u0, 6 b_u0,
//                  7 w_vi1, 8 w_u1, 9 b_u1
// ---------------------------------------------------------------------------
extern "C" void kernel_launch(void* const* d_in, const int* in_sizes, int n_in,
                              void* d_out, int out_size) {
    const float* v_i  = (const float*)d_in[0];
    const float* v_q  = (const float*)d_in[1];
    const float* l1_w = (const float*)d_in[2];
    const float* l1_b = (const float*)d_in[3];
    const float* w_vi0= (const float*)d_in[4];
    const float* w_u0 = (const float*)d_in[5];
    const float* b_u0 = (const float*)d_in[6];
    const float* w_vi1= (const float*)d_in[7];
    const float* w_u1 = (const float*)d_in[8];
    const float* b_u1 = (const float*)d_in[9];
    float* out = (float*)d_out;

    __half *p_a1, *p_vi, *p_z, *p_l1w, *p_wc;
    float *p_u0, *p_u1, *p_vqt;
    cudaGetSymbolAddress((void**)&p_a1,  g_a1);
    cudaGetSymbolAddress((void**)&p_vi,  g_vi);
    cudaGetSymbolAddress((void**)&p_z,   g_z);
    cudaGetSymbolAddress((void**)&p_l1w, g_l1w);
    cudaGetSymbolAddress((void**)&p_wc,  g_wc);
    cudaGetSymbolAddress((void**)&p_u0,  g_u0);
    cudaGetSymbolAddress((void**)&p_u1,  g_u1);
    cudaGetSymbolAddress((void**)&p_vqt, g_vqt);

    cudaFuncSetAttribute(k_mma_gemm<0>, cudaFuncAttributeMaxDynamicSharedMemorySize, SMEM_DYN);
    cudaFuncSetAttribute(k_mma_gemm<1>, cudaFuncAttributeMaxDynamicSharedMemorySize, SMEM_DYN);

    // 1: v_i transpose -> fp16
    {
        dim3 g(B_, C_ / 32, (S_ + 31) / 32);
        k_conv_vi<<<g, dim3(32, 8)>>>(v_i, p_a1);
    }
    // 2: l1_w -> fp16
    k_half<<<(HID_ * C_ + 255) / 256, 256>>>(l1_w, p_l1w, HID_ * C_);
    // 3: GEMM1 vi = tanh(A1 @ l1_w^T + l1_b) -> fp16
    {
        dim3 g(HID_ / 128, M_ / 128);
        k_mma_gemm<1><<<g, 256, SMEM_DYN>>>(p_a1, p_l1w, l1_b, nullptr, p_vi,
                                            C_, C_ / 64, HID_);
    }
    // 4: w0|w1 concat -> fp16
    k_half2src<<<(2 * HID_ * HID_ + 255) / 256, 256>>>(w_vi0, w_vi1, p_wc, HID_ * HID_);
    // 5: u0 = mean_t v_q
    k_mean_vq<<<B_, HID_>>>(v_q, p_u0);
    // 6: merged hop GEMM  z0|z1 = vi @ [w0|w1]^T  [M,2048] fp16
    {
        dim3 g(2 * HID_ / 128, M_ / 128);   // 16 x 196
        k_mma_gemm<0><<<g, 256, SMEM_DYN>>>(p_vi, p_wc, nullptr, p_z, nullptr,
                                            HID_, HID_ / 64, 2 * HID_);
    }
    // 7-10: attention chain
    k_vqt<<<B_ / 2, 256>>>(p_u0, w_u0, b_u0, p_vqt);
    k_attn<<<B_, 256>>>(p_z,        p_vi, p_vqt, p_u0, p_u1);
    k_vqt<<<B_ / 2, 256>>>(p_u1, w_u1, b_u1, p_vqt);
    k_attn<<<B_, 256>>>(p_z + HID_, p_vi, p_vqt, p_u1, out);
}